// round 10
// baseline (speedup 1.0000x reference)
#include <cuda_runtime.h>
#include <cuda_bf16.h>
#include <math.h>
#include <cstdint>

#define N_NODES 20000
#define N_EDGES 600000
#define HDIM 128
#define NHEADS 4
#define EB 4688   // ceil(600000/128)

// ---------------- scratch -----------------------------------------------------
__device__ float g_P[N_NODES * HDIM];
__device__ float g_num[N_NODES * HDIM];
__device__ float g_den[N_NODES * NHEADS];

// pre-split, pre-swizzled hE tiles: [block][chunk][16KB]
__device__ __align__(16) char g_hEh[(size_t)EB * 4 * 16384];
__device__ __align__(16) char g_hEl[(size_t)EB * 4 * 16384];

__device__ __align__(16) __nv_bfloat16 g_wv1h[32768], g_wv1l[32768];
__device__ __align__(16) __nv_bfloat16 g_wv2h[16384], g_wv2l[16384];
__device__ __align__(16) __nv_bfloat16 g_wv3h[16384], g_wv3l[16384];
__device__ __align__(16) __nv_bfloat16 g_wb1h[32768], g_wb1l[32768];
__device__ __align__(16) __nv_bfloat16 g_wb2h[16384], g_wb2l[16384];
__device__ __align__(16) __nv_bfloat16 g_wb3h[2048],  g_wb3l[2048];

// ---------------- helpers -----------------------------------------------------
__device__ __forceinline__ float gelu_f(float x) {
    return 0.5f * x * (1.0f + erff(x * 0.70710678118654752440f));
}
__device__ __forceinline__ void split2(float a, float b, unsigned &hi, unsigned &lo) {
    __nv_bfloat16 ha = __float2bfloat16(a), hb = __float2bfloat16(b);
    float ra = a - __bfloat162float(ha), rb = b - __bfloat162float(hb);
    __nv_bfloat162 th; th.x = ha; th.y = hb;
    __nv_bfloat162 tl = __floats2bfloat162_rn(ra, rb);
    hi = *reinterpret_cast<unsigned*>(&th);
    lo = *reinterpret_cast<unsigned*>(&tl);
}
__device__ __forceinline__ uint32_t smem_to_u32(const void* p) {
    uint32_t a;
    asm("{ .reg .u64 t; cvta.to.shared.u64 t, %1; cvt.u32.u64 %0, t; }" : "=r"(a) : "l"(p));
    return a;
}
__device__ __forceinline__ unsigned sw128(unsigned byte) {
    return byte ^ ((byte >> 3) & 0x70);
}

// ---------------- cp.async ------------------------------------------------------
__device__ __forceinline__ void cp16(uint32_t dst, const void* src) {
    asm volatile("cp.async.cg.shared.global [%0], [%1], 16;" :: "r"(dst), "l"(src));
}
#define CP_COMMIT() asm volatile("cp.async.commit_group;" ::: "memory")
#define CP_WAIT0()  asm volatile("cp.async.wait_group 0;" ::: "memory")
#define CP_WAIT1()  asm volatile("cp.async.wait_group 1;" ::: "memory")
#define CP_WAIT3()  asm volatile("cp.async.wait_group 3;" ::: "memory")

__device__ __forceinline__ void cpa16k(uint32_t dst, const char* src, int tid) {
#pragma unroll
    for (int j = 0; j < 4; ++j)
        cp16(dst + tid * 16 + j * 4096, src + tid * 16 + j * 4096);
}

// ---------------- mma.sync primitives ------------------------------------------
__device__ __forceinline__ void ldsm4(unsigned r[4], uint32_t addr) {
    asm volatile("ldmatrix.sync.aligned.m8n8.x4.shared.b16 {%0,%1,%2,%3}, [%4];"
        : "=r"(r[0]), "=r"(r[1]), "=r"(r[2]), "=r"(r[3]) : "r"(addr));
}
__device__ __forceinline__ void mma_bf16(float c[4], const unsigned a[4], const unsigned b[2]) {
    asm volatile("mma.sync.aligned.m16n8k16.row.col.f32.bf16.bf16.f32 "
        "{%0,%1,%2,%3}, {%4,%5,%6,%7}, {%8,%9}, {%0,%1,%2,%3};"
        : "+f"(c[0]), "+f"(c[1]), "+f"(c[2]), "+f"(c[3])
        : "r"(a[0]), "r"(a[1]), "r"(a[2]), "r"(a[3]), "r"(b[0]), "r"(b[1]));
}

// smem byte offsets (total 231936 <= 232448 optin)
#define OFF_CE   0
#define OFF_SEW  512
#define OFF_A    2560          /* 4 chunks x (16K h + 16K l) = 128K, 128B-aligned */
#define OFF_TB   133632        /* t1b/t2b tiles 64K; doubles as Wb1 stream bufs  */
#define OFF_S2   199168        /* W1v single buffer 32K                          */
#define SMEM_F   231936

// one K=64 chunk, 3-term split; tiles 128x64 bf16 SW128 (128B pitch)
__device__ __forceinline__ void chunk_mma(float acc[4][4][4],
                                          uint32_t Ah, uint32_t Al,
                                          uint32_t Bh, uint32_t Bl,
                                          int wm, int wn, int lid) {
    int g = lid >> 3, r = lid & 7;
    int am = (g & 1) * 8 + r, ak = (g >> 1) * 8;
    int bn = (g >> 1) * 8 + r, bk = (g & 1) * 8;
#pragma unroll
    for (int ks = 0; ks < 4; ++ks) {
        int kb = ks * 16;
        unsigned Af[2][4][4], Bf[2][4][2];
#pragma unroll
        for (int s = 0; s < 2; ++s) {
            uint32_t Ab = s ? Al : Ah;
#pragma unroll
            for (int ms = 0; ms < 4; ++ms) {
                unsigned byte = (unsigned)((wm * 64 + ms * 16 + am) * 128 + (kb + ak) * 2);
                ldsm4(Af[s][ms], Ab + sw128(byte));
            }
            uint32_t Bb = s ? Bl : Bh;
#pragma unroll
            for (int np = 0; np < 2; ++np) {
                unsigned byte = (unsigned)((wn * 32 + np * 16 + bn) * 128 + (kb + bk) * 2);
                unsigned t[4];
                ldsm4(t, Bb + sw128(byte));
                Bf[s][np*2][0] = t[0]; Bf[s][np*2][1] = t[1];
                Bf[s][np*2+1][0] = t[2]; Bf[s][np*2+1][1] = t[3];
            }
        }
#pragma unroll
        for (int ms = 0; ms < 4; ++ms)
#pragma unroll
            for (int ns = 0; ns < 4; ++ns) {
                mma_bf16(acc[ms][ns], Af[0][ms], Bf[0][ns]);
                mma_bf16(acc[ms][ns], Af[0][ms], Bf[1][ns]);
                mma_bf16(acc[ms][ns], Af[1][ms], Bf[0][ns]);
            }
    }
}

// logits variant: n0-7 only, B tile 16-row padded (2KB per h/l chunk)
__device__ __forceinline__ void chunk_mma_log(float accl[4][4],
                                              uint32_t Ah, uint32_t Al,
                                              uint32_t Bh, uint32_t Bl,
                                              int wm, int lid) {
    int g = lid >> 3, r = lid & 7;
    int am = (g & 1) * 8 + r, ak = (g >> 1) * 8;
    int bn = (g >> 1) * 8 + r, bk = (g & 1) * 8;
#pragma unroll
    for (int ks = 0; ks < 4; ++ks) {
        int kb = ks * 16;
        unsigned Af[2][4][4], Bf[2][2];
#pragma unroll
        for (int s = 0; s < 2; ++s) {
            uint32_t Ab = s ? Al : Ah;
#pragma unroll
            for (int ms = 0; ms < 4; ++ms) {
                unsigned byte = (unsigned)((wm * 64 + ms * 16 + am) * 128 + (kb + ak) * 2);
                ldsm4(Af[s][ms], Ab + sw128(byte));
            }
            unsigned byte = (unsigned)(bn * 128 + (kb + bk) * 2);
            unsigned t[4];
            ldsm4(t, (s ? Bl : Bh) + sw128(byte));
            Bf[s][0] = t[0]; Bf[s][1] = t[1];
        }
#pragma unroll
        for (int ms = 0; ms < 4; ++ms) {
            mma_bf16(accl[ms], Af[0][ms], Bf[0]);
            mma_bf16(accl[ms], Af[0][ms], Bf[1]);
            mma_bf16(accl[ms], Af[1][ms], Bf[0]);
        }
    }
}

// acc + add -> gelu -> split -> T tiles (hi @ +ch*16K, lo @ +32K+ch*16K)
__device__ __forceinline__ void epi_store(float acc[4][4][4], char* T,
                                          const float* __restrict__ addv,
                                          const int* __restrict__ ce, bool perrow,
                                          int wm, int wn, int lid) {
#pragma unroll
    for (int ms = 0; ms < 4; ++ms) {
        int r0 = wm * 64 + ms * 16 + (lid >> 2), r1 = r0 + 8;
#pragma unroll
        for (int ns = 0; ns < 4; ++ns) {
            int n = wn * 32 + ns * 8 + (lid & 3) * 2;
            const float* a0 = perrow ? (addv + (size_t)ce[r0] * 128 + n) : (addv + n);
            const float* a1 = perrow ? (addv + (size_t)ce[r1] * 128 + n) : (addv + n);
            float o0 = gelu_f(acc[ms][ns][0] + a0[0]);
            float o1 = gelu_f(acc[ms][ns][1] + a0[1]);
            float o2 = gelu_f(acc[ms][ns][2] + a1[0]);
            float o3 = gelu_f(acc[ms][ns][3] + a1[1]);
            unsigned h01, l01, h23, l23;
            split2(o0, o1, h01, l01);
            split2(o2, o3, h23, l23);
            int ch = n >> 6, kk = n & 63;
            unsigned s0 = sw128((unsigned)(r0 * 128 + kk * 2));
            unsigned s1 = sw128((unsigned)(r1 * 128 + kk * 2));
            char* th = T + ch * 16384;
            *(unsigned*)(th + s0) = h01;          *(unsigned*)(th + s1) = h23;
            *(unsigned*)(th + 32768 + s0) = l01;  *(unsigned*)(th + 32768 + s1) = l23;
        }
    }
}

#define ZERO_ACC(acc) do {                                                    \
    _Pragma("unroll") for (int _i = 0; _i < 4; ++_i)                          \
    _Pragma("unroll") for (int _j = 0; _j < 4; ++_j)                          \
    _Pragma("unroll") for (int _k = 0; _k < 4; ++_k) (acc)[_i][_j][_k] = 0.f; \
} while (0)

// ---------------- setup kernels -----------------------------------------------
extern "C" __global__ void __launch_bounds__(128)
k_init() {
    int i = blockIdx.x * blockDim.x + threadIdx.x;
    if (i < N_NODES * HDIM) g_num[i] = 0.0f;
    if (i < N_NODES * NHEADS) g_den[i] = 0.0f;
}

extern "C" __global__ void __launch_bounds__(256)
k_esplit(const float* __restrict__ hE) {
    const float4* hE4 = reinterpret_cast<const float4*>(hE);
    const size_t total = (size_t)EB * 128 * 64;
#pragma unroll
    for (int j = 0; j < 4; ++j) {
        size_t idx = (size_t)blockIdx.x * 1024 + j * 256 + threadIdx.x;
        if (idx >= total) continue;
        size_t e = idx >> 6; int q = (int)(idx & 63);
        int c = q >> 4, q15 = q & 15;
        int m = (int)(e & 127); size_t eb = e >> 7;
        float4 v = make_float4(0.f, 0.f, 0.f, 0.f);
        if (e < N_EDGES) v = hE4[e * 64 + (size_t)q];
        unsigned sw = sw128((unsigned)(m * 128 + q15 * 8));
        size_t tb = (eb * 4 + (size_t)c) * 16384;
        unsigned h01, l01, h23, l23;
        split2(v.x, v.y, h01, l01);
        split2(v.z, v.w, h23, l23);
        *(uint2*)(g_hEh + tb + sw) = make_uint2(h01, h23);
        *(uint2*)(g_hEl + tb + sw) = make_uint2(l01, l23);
    }
}

extern "C" __global__ void __launch_bounds__(256)
k_wconv(const float* __restrict__ W, __nv_bfloat16* __restrict__ hi,
        __nv_bfloat16* __restrict__ lo, int nrows_pad, int nrows_real,
        int nchunks, int rstride, int coff) {
    int idx = blockIdx.x * 256 + threadIdx.x;
    int tile = nrows_pad * 64;
    if (idx >= tile * nchunks) return;
    int c = idx / tile, rem = idx % tile;
    int n = rem / 64, kk = rem % 64;
    float x = (n < nrows_real) ? W[n * rstride + coff + c * 64 + kk] : 0.0f;
    __nv_bfloat16 h = __float2bfloat16(x);
    float r = x - __bfloat162float(h);
    unsigned sw = sw128((unsigned)(n * 128 + kk * 2));
    hi[c * tile + sw / 2] = h;
    lo[c * tile + sw / 2] = __float2bfloat16(r);
}

template<int K, int XP>
__device__ __forceinline__ void gemm_stage(float acc[64], const float* __restrict__ wrow,
                                           const float* __restrict__ xs) {
#pragma unroll 1
    for (int k = 0; k < K; k += 4) {
        float4 wv = *reinterpret_cast<const float4*>(wrow + k);
#pragma unroll
        for (int e = 0; e < 64; ++e) {
            float4 xv = *reinterpret_cast<const float4*>(xs + e * XP + k);
            acc[e] = fmaf(wv.x, xv.x, acc[e]);
            acc[e] = fmaf(wv.y, xv.y, acc[e]);
            acc[e] = fmaf(wv.z, xv.z, acc[e]);
            acc[e] = fmaf(wv.w, xv.w, acc[e]);
        }
    }
}

extern "C" __global__ void __launch_bounds__(128)
k_pre(const float* __restrict__ hV, const float* __restrict__ Wb1,
      const float* __restrict__ bb1) {
    __shared__ float xs[64 * HDIM];
    int j = threadIdx.x;
    int n0 = blockIdx.x * 64;
    int cnt = N_NODES - n0; if (cnt > 64) cnt = 64;
    const float4* src = reinterpret_cast<const float4*>(hV + (size_t)n0 * HDIM);
    float4* dst = reinterpret_cast<float4*>(xs);
    for (int i = j; i < 64 * HDIM / 4; i += 128) {
        int n = i / (HDIM / 4);
        dst[i] = (n < cnt) ? src[i] : make_float4(0.f, 0.f, 0.f, 0.f);
    }
    __syncthreads();
    float acc[64];
    float b = bb1[j];
#pragma unroll
    for (int e = 0; e < 64; ++e) acc[e] = b;
    gemm_stage<HDIM, HDIM>(acc, Wb1 + j * 384, xs);
#pragma unroll
    for (int e = 0; e < 64; ++e)
        if (e < cnt) g_P[(size_t)(n0 + e) * HDIM + j] = acc[e];
}

// ---------------- single fused edge kernel (sequential, A resident) ------------
extern "C" __global__ void __launch_bounds__(256)
k_edge_one(const int* __restrict__ cid,
           const float* __restrict__ bb2, const float* __restrict__ bb3,
           const float* __restrict__ bv1, const float* __restrict__ bv2,
           const float* __restrict__ bv3) {
    extern __shared__ char sm[];
    uint32_t smb = smem_to_u32(sm);
    int tid = threadIdx.x, wid = tid >> 5, lid = tid & 31;
    int wm = wid & 1, wn = wid >> 1;
    size_t e0 = (size_t)blockIdx.x * 128;
    size_t eb = (size_t)blockIdx.x;
    int* ce = (int*)(sm + OFF_CE);
    float* sew = (float*)(sm + OFF_SEW);
    if (tid < 128) ce[tid] = (e0 + tid < N_EDGES) ? cid[e0 + tid] : 0;

    const uint32_t A  = smb + OFF_A;            // chunk c: h @ A+c*32768, l @ +16384
    const uint32_t TB = smb + OFF_TB;           // 64K t1b/t2b; S0/S1 alias for Wb1
    const uint32_t S0 = TB, S1 = TB + 32768;
    const uint32_t S2 = smb + OFF_S2;           // 32K W1v buffer
    const uint32_t TV = A;                      // 64K t1v/t2v (A chunks 0,1 dead)
    const uint32_t W0 = A + 65536, W1 = A + 98304;  // W streams (A chunks 2,3 dead)

    float acc[4][4][4];
    ZERO_ACC(acc);

    // ===== bias L1: A streamed in (resident), Wb1 double-buffered S0/S1 =====
    cpa16k(A,          g_hEh + eb * 4 * 16384, tid);
    cpa16k(A + 16384,  g_hEl + eb * 4 * 16384, tid);
    cpa16k(S0,         (const char*)g_wb1h, tid);
    cpa16k(S0 + 16384, (const char*)g_wb1l, tid);
    CP_COMMIT();                                                   // G1: A0+Wb1_0
    cpa16k(A + 32768,  g_hEh + (eb * 4 + 1) * 16384, tid);
    cpa16k(A + 49152,  g_hEl + (eb * 4 + 1) * 16384, tid);
    cpa16k(S1,         (const char*)g_wb1h + 16384, tid);
    cpa16k(S1 + 16384, (const char*)g_wb1l + 16384, tid);
    CP_COMMIT();                                                   // G2: A1+Wb1_1
    cpa16k(A + 65536,  g_hEh + (eb * 4 + 2) * 16384, tid);
    cpa16k(A + 81920,  g_hEl + (eb * 4 + 2) * 16384, tid);
    CP_COMMIT();                                                   // G3: A2
    cpa16k(A + 98304,  g_hEh + (eb * 4 + 3) * 16384, tid);
    cpa16k(A + 114688, g_hEl + (eb * 4 + 3) * 16384, tid);
    CP_COMMIT();                                                   // G4: A3

    CP_WAIT3(); __syncthreads();                                   // G1 done
    chunk_mma(acc, A, A + 16384, S0, S0 + 16384, wm, wn, lid);
    __syncthreads();
    cpa16k(S0,         (const char*)g_wb1h + 32768, tid);
    cpa16k(S0 + 16384, (const char*)g_wb1l + 32768, tid);
    CP_COMMIT();                                                   // G5: Wb1_2
    CP_WAIT3(); __syncthreads();                                   // G2 done
    chunk_mma(acc, A + 32768, A + 49152, S1, S1 + 16384, wm, wn, lid);
    __syncthreads();
    cpa16k(S1,         (const char*)g_wb1h + 49152, tid);
    cpa16k(S1 + 16384, (const char*)g_wb1l + 49152, tid);
    CP_COMMIT();                                                   // G6: Wb1_3
    CP_WAIT1(); __syncthreads();                                   // G3,G4,G5 done
    chunk_mma(acc, A + 65536, A + 81920, S0, S0 + 16384, wm, wn, lid);
    __syncthreads();
    CP_WAIT0(); __syncthreads();                                   // G6 done
    chunk_mma(acc, A + 98304, A + 114688, S1, S1 + 16384, wm, wn, lid);
    __syncthreads();
    // t1b = gelu(D + P[ce]) -> TB (overwrites Wb1 stream bufs; Wb1 dead)
    epi_store(acc, sm + OFF_TB, g_P, ce, true, wm, wn, lid);
    __syncthreads();

    // ===== value L1: A resident, Wv1 single-buffered in S2 =====
    ZERO_ACC(acc);
    for (int c = 0; c < 4; ++c) {
        cpa16k(S2,         (const char*)g_wv1h + (size_t)c * 16384, tid);
        cpa16k(S2 + 16384, (const char*)g_wv1l + (size_t)c * 16384, tid);
        CP_COMMIT();
        CP_WAIT0(); __syncthreads();
        chunk_mma(acc, A + c * 32768, A + c * 32768 + 16384, S2, S2 + 16384, wm, wn, lid);
        __syncthreads();
    }
    // t1v = gelu(D + bv1) -> TV (A chunks 0,1 dead)
    epi_store(acc, sm + OFF_A, bv1, ce, false, wm, wn, lid);
    __syncthreads();

    // ===== bias L2: t1b @ Wb2^T (W dbl-buffered in W0/W1 = dead A2/A3) =====
    ZERO_ACC(acc);
    cpa16k(W0,         (const char*)g_wb2h, tid);
    cpa16k(W0 + 16384, (const char*)g_wb2l, tid);
    CP_COMMIT();
    cpa16k(W1,         (const char*)g_wb2h + 16384, tid);
    cpa16k(W1 + 16384, (const char*)g_wb2l + 16384, tid);
    CP_COMMIT();
    CP_WAIT1(); __syncthreads();
    chunk_mma(acc, TB, TB + 32768, W0, W0 + 16384, wm, wn, lid);
    CP_WAIT0(); __syncthreads();
    chunk_mma(acc, TB + 16384, TB + 49152, W1, W1 + 16384, wm, wn, lid);
    __syncthreads();
    epi_store(acc, sm + OFF_TB, bb2, ce, false, wm, wn, lid);   // t2b overwrites t1b
    __syncthreads();

    // ===== bias L3 logits (Wb3 8KB -> W0) + prefetch Wv2_0 -> W1 =====
    {
        const char* W3h = (const char*)g_wb3h;
        const char* W3l = (const char*)g_wb3l;
#pragma unroll
        for (int j = 0; j < 2; ++j) {
            int i = tid + j * 256;
            int quad = i >> 7, off = (i & 127) * 16;
            const char* src = (quad == 0) ? (W3h + off) :
                              (quad == 1) ? (W3l + off) :
                              (quad == 2) ? (W3h + 2048 + off) : (W3l + 2048 + off);
            cp16(W0 + quad * 2048 + off, src);
        }
        CP_COMMIT();
        cpa16k(W1,         (const char*)g_wv2h, tid);
        cpa16k(W1 + 16384, (const char*)g_wv2l, tid);
        CP_COMMIT();
        CP_WAIT1(); __syncthreads();   // Wb3 ready
    }
    {
        float accl[4][4];
#pragma unroll
        for (int i = 0; i < 4; ++i)
#pragma unroll
            for (int k = 0; k < 4; ++k) accl[i][k] = 0.f;
        if (wn == 0) {
            chunk_mma_log(accl, TB,         TB + 32768, W0,        W0 + 2048, wm, lid);
            chunk_mma_log(accl, TB + 16384, TB + 49152, W0 + 4096, W0 + 6144, wm, lid);
        }
        if (wn == 0 && (lid & 3) < 2) {
            const float rs = 0.17677669529663687f;  // 1/sqrt(32)
            int n = (lid & 3) * 2;
            float bn0 = bb3[n], bn1 = bb3[n + 1];
#pragma unroll
            for (int ms = 0; ms < 4; ++ms) {
                int r0 = wm * 64 + ms * 16 + (lid >> 2), r1 = r0 + 8;
                float w0 = expf((accl[ms][0] + bn0) * rs);
                float w1 = expf((accl[ms][1] + bn1) * rs);
                float w2 = expf((accl[ms][2] + bn0) * rs);
                float w3 = expf((accl[ms][3] + bn1) * rs);
                sew[r0 * 4 + n] = w0;  sew[r0 * 4 + n + 1] = w1;
                sew[r1 * 4 + n] = w2;  sew[r1 * 4 + n + 1] = w3;
                if (e0 + r0 < N_EDGES) {
                    atomicAdd(&g_den[(size_t)ce[r0] * 4 + n], w0);
                    atomicAdd(&g_den[(size_t)ce[r0] * 4 + n + 1], w1);
                }
                if (e0 + r1 < N_EDGES) {
                    atomicAdd(&g_den[(size_t)ce[r1] * 4 + n], w2);
                    atomicAdd(&g_den[(size_t)ce[r1] * 4 + n + 1], w3);
                }
            }
        }
    }
    CP_WAIT0(); __syncthreads();   // Wv2_0 ready; sew published

    // ===== value L2: t1v @ Wv2^T =====
    ZERO_ACC(acc);
    chunk_mma(acc, TV, TV + 32768, W1, W1 + 16384, wm, wn, lid);
    __syncthreads();
    cpa16k(W0,         (const char*)g_wv2h + 16384, tid);   // Wb3 dead
    cpa16k(W0 + 16384, (const char*)g_wv2l + 16384, tid);
    CP_COMMIT();
    CP_WAIT0(); __syncthreads();
    chunk_mma(acc, TV + 16384, TV + 49152, W0, W0 + 16384, wm, wn, lid);
    __syncthreads();
    epi_store(acc, sm + OFF_A, bv2, ce, false, wm, wn, lid);   // t2v overwrites t1v
    __syncthreads();

    // ===== value L3: V = t2v @ Wv3^T; exp-weighted scatter =====
    ZERO_ACC(acc);
    cpa16k(W1,         (const char*)g_wv3h, tid);
    cpa16k(W1 + 16384, (const char*)g_wv3l, tid);
    CP_COMMIT();
    cpa16k(W0,         (const char*)g_wv3h + 16384, tid);
    cpa16k(W0 + 16384, (const char*)g_wv3l + 16384, tid);
    CP_COMMIT();
    CP_WAIT1(); __syncthreads();
    chunk_mma(acc, TV, TV + 32768, W1, W1 + 16384, wm, wn, lid);
    CP_WAIT0(); __syncthreads();
    chunk_mma(acc, TV + 16384, TV + 49152, W0, W0 + 16384, wm, wn, lid);

#pragma unroll
    for (int ms = 0; ms < 4; ++ms) {
        int r0 = wm * 64 + ms * 16 + (lid >> 2), r1 = r0 + 8;
        float ew0 = sew[r0 * 4 + wn], ew1 = sew[r1 * 4 + wn];
        bool v0 = (e0 + r0) < N_EDGES, v1 = (e0 + r1) < N_EDGES;
        float* d0 = g_num + (size_t)ce[r0] * 128;
        float* d1 = g_num + (size_t)ce[r1] * 128;
#pragma unroll
        for (int ns = 0; ns < 4; ++ns) {
            int n = wn * 32 + ns * 8 + (lid & 3) * 2;
            float bn0 = bv3[n], bn1 = bv3[n + 1];
            if (v0) {
                atomicAdd(d0 + n,     ew0 * (acc[ms][ns][0] + bn0));
                atomicAdd(d0 + n + 1, ew0 * (acc[ms][ns][1] + bn1));
            }
            if (v1) {
                atomicAdd(d1 + n,     ew1 * (acc[ms][ns][2] + bn0));
                atomicAdd(d1 + n + 1, ew1 * (acc[ms][ns][3] + bn1));
            }
        }
    }
}

// ---------------- output projection --------------------------------------------
extern "C" __global__ void __launch_bounds__(128)
k_out(const float* __restrict__ Wo, float* __restrict__ out) {
    __shared__ float xs[64 * HDIM];
    int j = threadIdx.x;
    int n0 = blockIdx.x * 64;
    int cnt = N_NODES - n0; if (cnt > 64) cnt = 64;
    for (int i = j; i < 64 * HDIM; i += 128) {
        int n = i >> 7, c = i & 127;
        float v = 0.f;
        if (n < cnt) {
            float d = g_den[(size_t)(n0 + n) * NHEADS + (c >> 5)];
            float nm = g_num[(size_t)(n0 + n) * HDIM + c];
            v = (d > 0.f) ? nm / d : 0.f;
        }
        xs[i] = v;
    }
    __syncthreads();
    float acc[64];
#pragma unroll
    for (int e = 0; e < 64; ++e) acc[e] = 0.f;
    gemm_stage<HDIM, HDIM>(acc, Wo + j * HDIM, xs);
#pragma unroll
    for (int e = 0; e < 64; ++e)
        if (e < cnt) out[(size_t)(n0 + e) * HDIM + j] = acc[e];
}

// ---------------- launch --------------------------------------------------------
extern "C" void kernel_launch(void* const* d_in, const int* in_sizes, int n_in,
                              void* d_out, int out_size) {
    const float* hV  = (const float*)d_in[0];
    const float* hE  = (const float*)d_in[1];
    const float* Wv1 = (const float*)d_in[2];
    const float* bv1 = (const float*)d_in[3];
    const float* Wv2 = (const float*)d_in[4];
    const float* bv2 = (const float*)d_in[5];
    const float* Wv3 = (const float*)d_in[6];
    const float* bv3 = (const float*)d_in[7];
    const float* Wb1 = (const float*)d_in[8];
    const float* bb1 = (const float*)d_in[9];
    const float* Wb2 = (const float*)d_in[10];
    const float* bb2 = (const float*)d_in[11];
    const float* Wb3 = (const float*)d_in[12];
    const float* bb3 = (const float*)d_in[13];
    const float* Wo  = (const float*)d_in[14];
    const int*   cid = (const int*)d_in[15];
    float* out = (float*)d_out;

    __nv_bfloat16 *wv1h, *wv1l, *wv2h, *wv2l, *wv3h, *wv3l;
    __nv_bfloat16 *wb1h, *wb1l, *wb2h, *wb2l, *wb3h, *wb3l;
    cudaGetSymbolAddress((void**)&wv1h, g_wv1h); cudaGetSymbolAddress((void**)&wv1l, g_wv1l);
    cudaGetSymbolAddress((void**)&wv2h, g_wv2h); cudaGetSymbolAddress((void**)&wv2l, g_wv2l);
    cudaGetSymbolAddress((void**)&wv3h, g_wv3h); cudaGetSymbolAddress((void**)&wv3l, g_wv3l);
    cudaGetSymbolAddress((void**)&wb1h, g_wb1h); cudaGetSymbolAddress((void**)&wb1l, g_wb1l);
    cudaGetSymbolAddress((void**)&wb2h, g_wb2h); cudaGetSymbolAddress((void**)&wb2l, g_wb2l);
    cudaGetSymbolAddress((void**)&wb3h, g_wb3h); cudaGetSymbolAddress((void**)&wb3l, g_wb3l);

    cudaFuncSetAttribute(k_edge_one, cudaFuncAttributeMaxDynamicSharedMemorySize, SMEM_F);

    k_init<<<(N_NODES * HDIM + 127) / 128, 128>>>();
    k_wconv<<<128, 256>>>(Wv1, wv1h, wv1l, 128, 128, 4, 256, 0);
    k_wconv<<<64,  256>>>(Wv2, wv2h, wv2l, 128, 128, 2, 128, 0);
    k_wconv<<<64,  256>>>(Wv3, wv3h, wv3l, 128, 128, 2, 128, 0);
    k_wconv<<<128, 256>>>(Wb1, wb1h, wb1l, 128, 128, 4, 384, 128);
    k_wconv<<<64,  256>>>(Wb2, wb2h, wb2l, 128, 128, 2, 128, 0);
    k_wconv<<<8,   256>>>(Wb3, wb3h, wb3l, 16, 4, 2, 128, 0);
    k_esplit<<<(EB * 128 * 64 + 1023) / 1024, 256>>>(hE);
    k_pre<<<(N_NODES + 63) / 64, 128>>>(hV, Wb1, bb1);

    k_edge_one<<<EB, 256, SMEM_F>>>(cid, bb2, bb3, bv1, bv2, bv3);
    k_out<<<(N_NODES + 63) / 64, 128>>>(Wo, out);
}

// round 11
// speedup vs baseline: 2.2415x; 2.2415x over previous
#include <cuda_runtime.h>
#include <cuda_fp16.h>
#include <math.h>
#include <cstdint>

#define N_NODES 20000
#define N_EDGES 600000
#define HDIM 128
#define NHEADS 4
#define EB 4688   // ceil(600000/128)

// ---------------- scratch -----------------------------------------------------
__device__ float g_P[N_NODES * HDIM];
__device__ float g_num[N_NODES * HDIM];
__device__ float g_den[N_NODES * NHEADS];
__device__ float g_ew[(size_t)EB * 128 * NHEADS];   // padded per-edge exp weights

// pre-converted, pre-swizzled fp16 hE tiles: [block][chunk][16KB]
__device__ __align__(16) char g_hEf[(size_t)EB * 4 * 16384];

__device__ __align__(16) __half g_wv1f[32768];
__device__ __align__(16) __half g_wv2f[16384];
__device__ __align__(16) __half g_wv3f[16384];
__device__ __align__(16) __half g_wb1f[32768];
__device__ __align__(16) __half g_wb2f[16384];
__device__ __align__(16) __half g_wb3f[2048];

// ---------------- helpers -----------------------------------------------------
__device__ __forceinline__ float gelu_f(float x) {
    return 0.5f * x * (1.0f + erff(x * 0.70710678118654752440f));
}
__device__ __forceinline__ uint32_t smem_to_u32(const void* p) {
    uint32_t a;
    asm("{ .reg .u64 t; cvta.to.shared.u64 t, %1; cvt.u32.u64 %0, t; }" : "=r"(a) : "l"(p));
    return a;
}
__device__ __forceinline__ unsigned sw128(unsigned byte) {
    return byte ^ ((byte >> 3) & 0x70);
}
__device__ __forceinline__ unsigned pack_h2(float a, float b) {
    __half2 h = __floats2half2_rn(a, b);
    return *reinterpret_cast<unsigned*>(&h);
}

// ---------------- cp.async ------------------------------------------------------
__device__ __forceinline__ void cp16(uint32_t dst, const void* src) {
    asm volatile("cp.async.cg.shared.global [%0], [%1], 16;" :: "r"(dst), "l"(src));
}
#define CP_COMMIT() asm volatile("cp.async.commit_group;" ::: "memory")
#define CP_WAIT0()  asm volatile("cp.async.wait_group 0;" ::: "memory")
#define CP_WAIT1()  asm volatile("cp.async.wait_group 1;" ::: "memory")

__device__ __forceinline__ void cpa16k(uint32_t dst, const char* src, int tid) {
#pragma unroll
    for (int j = 0; j < 4; ++j)
        cp16(dst + tid * 16 + j * 4096, src + tid * 16 + j * 4096);
}

// ---------------- mma.sync primitives ------------------------------------------
__device__ __forceinline__ void ldsm4(unsigned r[4], uint32_t addr) {
    asm volatile("ldmatrix.sync.aligned.m8n8.x4.shared.b16 {%0,%1,%2,%3}, [%4];"
        : "=r"(r[0]), "=r"(r[1]), "=r"(r[2]), "=r"(r[3]) : "r"(addr));
}
__device__ __forceinline__ void mma_f16(float c[4], const unsigned a[4], const unsigned b[2]) {
    asm volatile("mma.sync.aligned.m16n8k16.row.col.f32.f16.f16.f32 "
        "{%0,%1,%2,%3}, {%4,%5,%6,%7}, {%8,%9}, {%0,%1,%2,%3};"
        : "+f"(c[0]), "+f"(c[1]), "+f"(c[2]), "+f"(c[3])
        : "r"(a[0]), "r"(a[1]), "r"(a[2]), "r"(a[3]), "r"(b[0]), "r"(b[1]));
}

// smem byte offsets (total 102400 -> 2 CTAs/SM)
#define OFF_CE   0
#define OFF_SEW  512
#define OFF_B0   4096
#define OFF_B1   20480
#define OFF_A0   36864
#define OFF_A1   53248
#define OFF_T    69632      /* 2 chunks x 16KB */
#define SMEM_E   102400

// one K=64 chunk, single fp16 pass; tiles 128x64 fp16 SW128 (128B pitch)
__device__ __forceinline__ void chunk_mma(float acc[4][4][4],
                                          uint32_t A, uint32_t B,
                                          int wm, int wn, int lid) {
    int g = lid >> 3, r = lid & 7;
    int am = (g & 1) * 8 + r, ak = (g >> 1) * 8;
    int bn = (g >> 1) * 8 + r, bk = (g & 1) * 8;
#pragma unroll
    for (int ks = 0; ks < 4; ++ks) {
        int kb = ks * 16;
        unsigned Af[4][4], Bf[4][2];
#pragma unroll
        for (int ms = 0; ms < 4; ++ms) {
            unsigned byte = (unsigned)((wm * 64 + ms * 16 + am) * 128 + (kb + ak) * 2);
            ldsm4(Af[ms], A + sw128(byte));
        }
#pragma unroll
        for (int np = 0; np < 2; ++np) {
            unsigned byte = (unsigned)((wn * 32 + np * 16 + bn) * 128 + (kb + bk) * 2);
            unsigned t[4];
            ldsm4(t, B + sw128(byte));
            Bf[np*2][0] = t[0]; Bf[np*2][1] = t[1];
            Bf[np*2+1][0] = t[2]; Bf[np*2+1][1] = t[3];
        }
#pragma unroll
        for (int ms = 0; ms < 4; ++ms)
#pragma unroll
            for (int ns = 0; ns < 4; ++ns)
                mma_f16(acc[ms][ns], Af[ms], Bf[ns]);
    }
}

// logits variant: n0-7 only, B tile 16-row padded (2KB per chunk)
__device__ __forceinline__ void chunk_mma_log(float accl[4][4],
                                              uint32_t A, uint32_t B,
                                              int wm, int lid) {
    int g = lid >> 3, r = lid & 7;
    int am = (g & 1) * 8 + r, ak = (g >> 1) * 8;
    int bn = (g >> 1) * 8 + r, bk = (g & 1) * 8;
#pragma unroll
    for (int ks = 0; ks < 4; ++ks) {
        int kb = ks * 16;
        unsigned Af[4][4], Bf[2];
#pragma unroll
        for (int ms = 0; ms < 4; ++ms) {
            unsigned byte = (unsigned)((wm * 64 + ms * 16 + am) * 128 + (kb + ak) * 2);
            ldsm4(Af[ms], A + sw128(byte));
        }
        unsigned byte = (unsigned)(bn * 128 + (kb + bk) * 2);
        unsigned t[4];
        ldsm4(t, B + sw128(byte));
        Bf[0] = t[0]; Bf[1] = t[1];
#pragma unroll
        for (int ms = 0; ms < 4; ++ms)
            mma_f16(accl[ms], Af[ms], Bf);
    }
}

// acc + add -> gelu -> fp16 -> T tiles (chunk ch @ +ch*16K)
__device__ __forceinline__ void epi_store(float acc[4][4][4], char* T,
                                          const float* __restrict__ addv,
                                          const int* __restrict__ ce, bool perrow,
                                          int wm, int wn, int lid) {
#pragma unroll
    for (int ms = 0; ms < 4; ++ms) {
        int r0 = wm * 64 + ms * 16 + (lid >> 2), r1 = r0 + 8;
#pragma unroll
        for (int ns = 0; ns < 4; ++ns) {
            int n = wn * 32 + ns * 8 + (lid & 3) * 2;
            const float* a0 = perrow ? (addv + (size_t)ce[r0] * 128 + n) : (addv + n);
            const float* a1 = perrow ? (addv + (size_t)ce[r1] * 128 + n) : (addv + n);
            float o0 = gelu_f(acc[ms][ns][0] + a0[0]);
            float o1 = gelu_f(acc[ms][ns][1] + a0[1]);
            float o2 = gelu_f(acc[ms][ns][2] + a1[0]);
            float o3 = gelu_f(acc[ms][ns][3] + a1[1]);
            int ch = n >> 6, kk = n & 63;
            char* th = T + ch * 16384;
            *(unsigned*)(th + sw128((unsigned)(r0 * 128 + kk * 2))) = pack_h2(o0, o1);
            *(unsigned*)(th + sw128((unsigned)(r1 * 128 + kk * 2))) = pack_h2(o2, o3);
        }
    }
}

#define ZERO_ACC(acc) do {                                                    \
    _Pragma("unroll") for (int _i = 0; _i < 4; ++_i)                          \
    _Pragma("unroll") for (int _j = 0; _j < 4; ++_j)                          \
    _Pragma("unroll") for (int _k = 0; _k < 4; ++_k) (acc)[_i][_j][_k] = 0.f; \
} while (0)

// ---------------- setup kernels -----------------------------------------------
extern "C" __global__ void __launch_bounds__(128)
k_init() {
    int i = blockIdx.x * blockDim.x + threadIdx.x;
    if (i < N_NODES * HDIM) g_num[i] = 0.0f;
    if (i < N_NODES * NHEADS) g_den[i] = 0.0f;
}

// hE -> pre-swizzled fp16 tiles
extern "C" __global__ void __launch_bounds__(256)
k_econv(const float* __restrict__ hE) {
    const float4* hE4 = reinterpret_cast<const float4*>(hE);
    const size_t total = (size_t)EB * 128 * 64;
#pragma unroll
    for (int j = 0; j < 4; ++j) {
        size_t idx = (size_t)blockIdx.x * 1024 + j * 256 + threadIdx.x;
        if (idx >= total) continue;
        size_t e = idx >> 6; int q = (int)(idx & 63);
        int c = q >> 4, q15 = q & 15;
        int m = (int)(e & 127); size_t eb = e >> 7;
        float4 v = make_float4(0.f, 0.f, 0.f, 0.f);
        if (e < N_EDGES) v = hE4[e * 64 + (size_t)q];
        unsigned sw = sw128((unsigned)(m * 128 + q15 * 8));
        size_t tb = (eb * 4 + (size_t)c) * 16384;
        *(uint2*)(g_hEf + tb + sw) = make_uint2(pack_h2(v.x, v.y), pack_h2(v.z, v.w));
    }
}

extern "C" __global__ void __launch_bounds__(256)
k_wconv(const float* __restrict__ W, __half* __restrict__ out,
        int nrows_pad, int nrows_real, int nchunks, int rstride, int coff) {
    int idx = blockIdx.x * 256 + threadIdx.x;
    int tile = nrows_pad * 64;
    if (idx >= tile * nchunks) return;
    int c = idx / tile, rem = idx % tile;
    int n = rem / 64, kk = rem % 64;
    float x = (n < nrows_real) ? W[n * rstride + coff + c * 64 + kk] : 0.0f;
    unsigned sw = sw128((unsigned)(n * 128 + kk * 2));
    out[c * tile + sw / 2] = __float2half_rn(x);
}

template<int K, int XP>
__device__ __forceinline__ void gemm_stage(float acc[64], const float* __restrict__ wrow,
                                           const float* __restrict__ xs) {
#pragma unroll 1
    for (int k = 0; k < K; k += 4) {
        float4 wv = *reinterpret_cast<const float4*>(wrow + k);
#pragma unroll
        for (int e = 0; e < 64; ++e) {
            float4 xv = *reinterpret_cast<const float4*>(xs + e * XP + k);
            acc[e] = fmaf(wv.x, xv.x, acc[e]);
            acc[e] = fmaf(wv.y, xv.y, acc[e]);
            acc[e] = fmaf(wv.z, xv.z, acc[e]);
            acc[e] = fmaf(wv.w, xv.w, acc[e]);
        }
    }
}

extern "C" __global__ void __launch_bounds__(128)
k_pre(const float* __restrict__ hV, const float* __restrict__ Wb1,
      const float* __restrict__ bb1) {
    __shared__ float xs[64 * HDIM];
    int j = threadIdx.x;
    int n0 = blockIdx.x * 64;
    int cnt = N_NODES - n0; if (cnt > 64) cnt = 64;
    const float4* src = reinterpret_cast<const float4*>(hV + (size_t)n0 * HDIM);
    float4* dst = reinterpret_cast<float4*>(xs);
    for (int i = j; i < 64 * HDIM / 4; i += 128) {
        int n = i / (HDIM / 4);
        dst[i] = (n < cnt) ? src[i] : make_float4(0.f, 0.f, 0.f, 0.f);
    }
    __syncthreads();
    float acc[64];
    float b = bb1[j];
#pragma unroll
    for (int e = 0; e < 64; ++e) acc[e] = b;
    gemm_stage<HDIM, HDIM>(acc, Wb1 + j * 384, xs);
#pragma unroll
    for (int e = 0; e < 64; ++e)
        if (e < cnt) g_P[(size_t)(n0 + e) * HDIM + j] = acc[e];
}

// ---------------- edge kernel (two-pass, fp16, 2 CTAs/SM) ----------------------
// mode 1 = bias MLP (-> g_ew, g_den); mode 0 = value MLP (-> scatter g_num)
extern "C" __global__ void __launch_bounds__(256, 2)
k_edge(int mode, const int* __restrict__ cid,
       const float* __restrict__ b1, const float* __restrict__ b2,
       const float* __restrict__ b3) {
    extern __shared__ char sm[];
    uint32_t smb = smem_to_u32(sm);
    int tid = threadIdx.x, wid = tid >> 5, lid = tid & 31;
    int wm = wid & 1, wn = wid >> 1;
    size_t e0 = (size_t)blockIdx.x * 128;
    size_t eb = (size_t)blockIdx.x;
    int* ce = (int*)(sm + OFF_CE);
    float* sew = (float*)(sm + OFF_SEW);
    if (tid < 128) ce[tid] = (e0 + tid < N_EDGES) ? cid[e0 + tid] : 0;

    const char* W1 = (const char*)(mode ? g_wb1f : g_wv1f);
    const char* W2 = (const char*)(mode ? g_wb2f : g_wv2f);
    const uint32_t A0 = smb + OFF_A0, A1 = smb + OFF_A1;
    const uint32_t B0 = smb + OFF_B0, B1 = smb + OFF_B1;
    const uint32_t T  = smb + OFF_T;

    float acc[4][4][4];
    ZERO_ACC(acc);

    // ---- L1: hE @ W1^T (K=256, 4 chunks, double-buffered) ----
    cpa16k(A0, g_hEf + eb * 4 * 16384, tid);
    cpa16k(B0, W1, tid);
    CP_COMMIT();                                               // G1
    cpa16k(A1, g_hEf + (eb * 4 + 1) * 16384, tid);
    cpa16k(B1, W1 + 16384, tid);
    CP_COMMIT();                                               // G2
    CP_WAIT1(); __syncthreads();                               // G1 done
    chunk_mma(acc, A0, B0, wm, wn, lid);
    __syncthreads();
    cpa16k(A0, g_hEf + (eb * 4 + 2) * 16384, tid);
    cpa16k(B0, W1 + 32768, tid);
    CP_COMMIT();                                               // G3
    CP_WAIT1(); __syncthreads();                               // G2 done
    chunk_mma(acc, A1, B1, wm, wn, lid);
    __syncthreads();
    cpa16k(A1, g_hEf + (eb * 4 + 3) * 16384, tid);
    cpa16k(B1, W1 + 49152, tid);
    CP_COMMIT();                                               // G4
    CP_WAIT1(); __syncthreads();                               // G3 done
    chunk_mma(acc, A0, B0, wm, wn, lid);
    __syncthreads();
    cpa16k(B0, W2, tid);
    CP_COMMIT();                                               // G5
    CP_WAIT1(); __syncthreads();                               // G4 done
    chunk_mma(acc, A1, B1, wm, wn, lid);
    __syncthreads();
    cpa16k(B1, W2 + 16384, tid);
    CP_COMMIT();                                               // G6
    // t1 = gelu(D + (P[ce] | bv1)) -> T
    epi_store(acc, sm + OFF_T, mode ? g_P : b1, ce, mode != 0, wm, wn, lid);
    __syncthreads();

    // ---- L2: t1 @ W2^T ----
    ZERO_ACC(acc);
    CP_WAIT1(); __syncthreads();                               // G5 done
    chunk_mma(acc, T, B0, wm, wn, lid);
    CP_WAIT0(); __syncthreads();                               // G6 done
    chunk_mma(acc, T + 16384, B1, wm, wn, lid);
    __syncthreads();

    // ---- L3 ----
    if (mode) {
        // Wb3 (4KB) -> B0, overlapped with t2 epilogue
        cp16(B0 + tid * 16, (const char*)g_wb3f + tid * 16);
        CP_COMMIT();
        epi_store(acc, sm + OFF_T, b2, ce, false, wm, wn, lid);   // t2 -> T
        __syncthreads();
        CP_WAIT0(); __syncthreads();
        float accl[4][4];
#pragma unroll
        for (int i = 0; i < 4; ++i)
#pragma unroll
            for (int k = 0; k < 4; ++k) accl[i][k] = 0.f;
        if (wn == 0) {
            chunk_mma_log(accl, T, B0, wm, lid);
            chunk_mma_log(accl, T + 16384, B0 + 2048, wm, lid);
        }
        if (wn == 0 && (lid & 3) < 2) {
            const float rs = 0.17677669529663687f;  // 1/sqrt(32)
            int n = (lid & 3) * 2;
            float bn0 = b3[n], bn1 = b3[n + 1];
#pragma unroll
            for (int ms = 0; ms < 4; ++ms) {
                int r0 = wm * 64 + ms * 16 + (lid >> 2), r1 = r0 + 8;
                float w0 = expf((accl[ms][0] + bn0) * rs);
                float w1 = expf((accl[ms][1] + bn1) * rs);
                float w2 = expf((accl[ms][2] + bn0) * rs);
                float w3 = expf((accl[ms][3] + bn1) * rs);
                g_ew[(e0 + r0) * 4 + n] = w0;
                g_ew[(e0 + r0) * 4 + n + 1] = w1;
                g_ew[(e0 + r1) * 4 + n] = w2;
                g_ew[(e0 + r1) * 4 + n + 1] = w3;
                if (e0 + r0 < N_EDGES) {
                    atomicAdd(&g_den[(size_t)ce[r0] * 4 + n], w0);
                    atomicAdd(&g_den[(size_t)ce[r0] * 4 + n + 1], w1);
                }
                if (e0 + r1 < N_EDGES) {
                    atomicAdd(&g_den[(size_t)ce[r1] * 4 + n], w2);
                    atomicAdd(&g_den[(size_t)ce[r1] * 4 + n + 1], w3);
                }
            }
        }
    } else {
        // Wv3 loads overlapped with t2 epilogue + ew fetch
        cpa16k(B0, (const char*)g_wv3f, tid);
        CP_COMMIT();                                            // G7
        cpa16k(B1, (const char*)g_wv3f + 16384, tid);
        CP_COMMIT();                                            // G8
        epi_store(acc, sm + OFF_T, b2, ce, false, wm, wn, lid);    // t2 -> T
        if (tid < 128)
            *(float4*)(sew + tid * 4) = *(const float4*)(g_ew + (e0 + tid) * 4);
        __syncthreads();
        ZERO_ACC(acc);
        CP_WAIT1(); __syncthreads();                            // G7 done
        chunk_mma(acc, T, B0, wm, wn, lid);
        CP_WAIT0(); __syncthreads();                            // G8 done
        chunk_mma(acc, T + 16384, B1, wm, wn, lid);

#pragma unroll
        for (int ms = 0; ms < 4; ++ms) {
            int r0 = wm * 64 + ms * 16 + (lid >> 2), r1 = r0 + 8;
            float ew0 = sew[r0 * 4 + wn], ew1 = sew[r1 * 4 + wn];
            bool v0 = (e0 + r0) < N_EDGES, v1 = (e0 + r1) < N_EDGES;
            float* d0 = g_num + (size_t)ce[r0] * 128;
            float* d1 = g_num + (size_t)ce[r1] * 128;
#pragma unroll
            for (int ns = 0; ns < 4; ++ns) {
                int n = wn * 32 + ns * 8 + (lid & 3) * 2;
                float bn0 = b3[n], bn1 = b3[n + 1];
                if (v0) {
                    atomicAdd(d0 + n,     ew0 * (acc[ms][ns][0] + bn0));
                    atomicAdd(d0 + n + 1, ew0 * (acc[ms][ns][1] + bn1));
                }
                if (v1) {
                    atomicAdd(d1 + n,     ew1 * (acc[ms][ns][2] + bn0));
                    atomicAdd(d1 + n + 1, ew1 * (acc[ms][ns][3] + bn1));
                }
            }
        }
    }
}

// ---------------- output projection --------------------------------------------
extern "C" __global__ void __launch_bounds__(128)
k_out(const float* __restrict__ Wo, float* __restrict__ out) {
    __shared__ float xs[64 * HDIM];
    int j = threadIdx.x;
    int n0 = blockIdx.x * 64;
    int cnt = N_NODES - n0; if (cnt > 64) cnt = 64;
    for (int i = j; i < 64 * HDIM; i += 128) {
        int n = i >> 7, c = i & 127;
        float v = 0.f;
        if (n < cnt) {
            float d = g_den[(size_t)(n0 + n) * NHEADS + (c >> 5)];
            float nm = g_num[(size_t)(n0 + n) * HDIM + c];
            v = (d > 0.f) ? nm / d : 0.f;
        }
        xs[i] = v;
    }
    __syncthreads();
    float acc[64];
#pragma unroll
    for (int e = 0; e < 64; ++e) acc[e] = 0.f;
    gemm_stage<HDIM, HDIM>(acc, Wo + j * HDIM, xs);
#pragma unroll
    for (int e = 0; e < 64; ++e)
        if (e < cnt) out[(size_t)(n0 + e) * HDIM + j] = acc[e];
}

// ---------------- launch --------------------------------------------------------
extern "C" void kernel_launch(void* const* d_in, const int* in_sizes, int n_in,
                              void* d_out, int out_size) {
    const float* hV  = (const float*)d_in[0];
    const float* hE  = (const float*)d_in[1];
    const float* Wv1 = (const float*)d_in[2];
    const float* bv1 = (const float*)d_in[3];
    const float* Wv2 = (const float*)d_in[4];
    const float* bv2 = (const float*)d_in[5];
    const float* Wv3 = (const float*)d_in[6];
    const float* bv3 = (const float*)d_in[7];
    const float* Wb1 = (const float*)d_in[8];
    const float* bb1 = (const float*)d_in[9];
    const float* Wb2 = (const float*)d_in[10];
    const float* bb2 = (const float*)d_in[11];
    const float* Wb3 = (const float*)d_in[12];
    const float* bb3 = (const float*)d_in[13];
    const float* Wo  = (const float*)d_in[14];
    const int*   cid = (const int*)d_in[15];
    float* out = (float*)d_out;

    __half *wv1f, *wv2f, *wv3f, *wb1f, *wb2f, *wb3f;
    cudaGetSymbolAddress((void**)&wv1f, g_wv1f);
    cudaGetSymbolAddress((void**)&wv2f, g_wv2f);
    cudaGetSymbolAddress((void**)&wv3f, g_wv3f);
    cudaGetSymbolAddress((void**)&wb1f, g_wb1f);
    cudaGetSymbolAddress((void**)&wb2f, g_wb2f);
    cudaGetSymbolAddress((void**)&wb3f, g_wb3f);

    cudaFuncSetAttribute(k_edge, cudaFuncAttributeMaxDynamicSharedMemorySize, SMEM_E);

    k_init<<<(N_NODES * HDIM + 127) / 128, 128>>>();
    k_wconv<<<128, 256>>>(Wv1, wv1f, 128, 128, 4, 256, 0);
    k_wconv<<<64,  256>>>(Wv2, wv2f, 128, 128, 2, 128, 0);
    k_wconv<<<64,  256>>>(Wv3, wv3f, 128, 128, 2, 128, 0);
    k_wconv<<<128, 256>>>(Wb1, wb1f, 128, 128, 4, 384, 128);
    k_wconv<<<64,  256>>>(Wb2, wb2f, 128, 128, 2, 128, 0);
    k_wconv<<<8,   256>>>(Wb3, wb3f, 16, 4, 2, 128, 0);
    k_econv<<<(EB * 128 * 64 + 1023) / 1024, 256>>>(hE);
    k_pre<<<(N_NODES + 63) / 64, 128>>>(hV, Wb1, bb1);

    k_edge<<<EB, 256, SMEM_E>>>(1, cid, bb1, bb2, bb3);   // bias MLP -> ew, den
    k_edge<<<EB, 256, SMEM_E>>>(0, cid, bv1, bv2, bv3);   // value MLP -> num
    k_out<<<(N_NODES + 63) / 64, 128>>>(Wo, out);
}

// round 12
// speedup vs baseline: 2.3173x; 1.0339x over previous
#include <cuda_runtime.h>
#include <cuda_fp16.h>
#include <math.h>
#include <cstdint>

#define N_NODES 20000
#define N_EDGES 600000
#define HDIM 128
#define NHEADS 4
#define EB 4688   // ceil(600000/128)

// ---------------- scratch -----------------------------------------------------
__device__ float g_P[N_NODES * HDIM];
__device__ float g_num[N_NODES * HDIM];
__device__ float g_den[N_NODES * NHEADS];
__device__ float g_ew[(size_t)EB * 128 * NHEADS];   // padded per-edge exp weights

// pre-converted, pre-swizzled fp16 hE tiles: [block][chunk][16KB]
__device__ __align__(16) char g_hEf[(size_t)EB * 4 * 16384];

__device__ __align__(16) __half g_wv1f[32768];
__device__ __align__(16) __half g_wv2f[16384];
__device__ __align__(16) __half g_wv3f[16384];
__device__ __align__(16) __half g_wb1f[32768];
__device__ __align__(16) __half g_wb2f[16384];
__device__ __align__(16) __half g_wb3f[2048];

// ---------------- helpers -----------------------------------------------------
__device__ __forceinline__ float gelu_f(float x) {
    return 0.5f * x * (1.0f + erff(x * 0.70710678118654752440f));
}
__device__ __forceinline__ uint32_t smem_to_u32(const void* p) {
    uint32_t a;
    asm("{ .reg .u64 t; cvta.to.shared.u64 t, %1; cvt.u32.u64 %0, t; }" : "=r"(a) : "l"(p));
    return a;
}
__device__ __forceinline__ unsigned sw128(unsigned byte) {
    return byte ^ ((byte >> 3) & 0x70);
}
__device__ __forceinline__ unsigned pack_h2(float a, float b) {
    __half2 h = __floats2half2_rn(a, b);
    return *reinterpret_cast<unsigned*>(&h);
}
// vectorized global reduction (base PTX, sm_90+)
__device__ __forceinline__ void red2(float* addr, float a, float b) {
    asm volatile("red.global.add.v2.f32 [%0], {%1, %2};"
                 :: "l"(addr), "f"(a), "f"(b) : "memory");
}

// ---------------- cp.async ------------------------------------------------------
__device__ __forceinline__ void cp16(uint32_t dst, const void* src) {
    asm volatile("cp.async.cg.shared.global [%0], [%1], 16;" :: "r"(dst), "l"(src));
}
#define CP_COMMIT() asm volatile("cp.async.commit_group;" ::: "memory")
#define CP_WAIT0()  asm volatile("cp.async.wait_group 0;" ::: "memory")
#define CP_WAIT1()  asm volatile("cp.async.wait_group 1;" ::: "memory")

__device__ __forceinline__ void cpa16k(uint32_t dst, const char* src, int tid) {
#pragma unroll
    for (int j = 0; j < 4; ++j)
        cp16(dst + tid * 16 + j * 4096, src + tid * 16 + j * 4096);
}

// ---------------- mma.sync primitives ------------------------------------------
__device__ __forceinline__ void ldsm4(unsigned r[4], uint32_t addr) {
    asm volatile("ldmatrix.sync.aligned.m8n8.x4.shared.b16 {%0,%1,%2,%3}, [%4];"
        : "=r"(r[0]), "=r"(r[1]), "=r"(r[2]), "=r"(r[3]) : "r"(addr));
}
__device__ __forceinline__ void mma_f16(float c[4], const unsigned a[4], const unsigned b[2]) {
    asm volatile("mma.sync.aligned.m16n8k16.row.col.f32.f16.f16.f32 "
        "{%0,%1,%2,%3}, {%4,%5,%6,%7}, {%8,%9}, {%0,%1,%2,%3};"
        : "+f"(c[0]), "+f"(c[1]), "+f"(c[2]), "+f"(c[3])
        : "r"(a[0]), "r"(a[1]), "r"(a[2]), "r"(a[3]), "r"(b[0]), "r"(b[1]));
}

// smem byte offsets (total 102400 -> 2 CTAs/SM)
#define OFF_CE   0
#define OFF_SEW  512
#define OFF_B0   4096
#define OFF_B1   20480
#define OFF_A0   36864
#define OFF_A1   53248
#define OFF_T    69632      /* 2 chunks x 16KB */
#define SMEM_E   102400

// one K=64 chunk, single fp16 pass; tiles 128x64 fp16 SW128 (128B pitch)
__device__ __forceinline__ void chunk_mma(float acc[4][4][4],
                                          uint32_t A, uint32_t B,
                                          int wm, int wn, int lid) {
    int g = lid >> 3, r = lid & 7;
    int am = (g & 1) * 8 + r, ak = (g >> 1) * 8;
    int bn = (g >> 1) * 8 + r, bk = (g & 1) * 8;
#pragma unroll
    for (int ks = 0; ks < 4; ++ks) {
        int kb = ks * 16;
        unsigned Af[4][4], Bf[4][2];
#pragma unroll
        for (int ms = 0; ms < 4; ++ms) {
            unsigned byte = (unsigned)((wm * 64 + ms * 16 + am) * 128 + (kb + ak) * 2);
            ldsm4(Af[ms], A + sw128(byte));
        }
#pragma unroll
        for (int np = 0; np < 2; ++np) {
            unsigned byte = (unsigned)((wn * 32 + np * 16 + bn) * 128 + (kb + bk) * 2);
            unsigned t[4];
            ldsm4(t, B + sw128(byte));
            Bf[np*2][0] = t[0]; Bf[np*2][1] = t[1];
            Bf[np*2+1][0] = t[2]; Bf[np*2+1][1] = t[3];
        }
#pragma unroll
        for (int ms = 0; ms < 4; ++ms)
#pragma unroll
            for (int ns = 0; ns < 4; ++ns)
                mma_f16(acc[ms][ns], Af[ms], Bf[ns]);
    }
}

// logits variant: n0-7 only, B tile 16-row padded (2KB per chunk)
__device__ __forceinline__ void chunk_mma_log(float accl[4][4],
                                              uint32_t A, uint32_t B,
                                              int wm, int lid) {
    int g = lid >> 3, r = lid & 7;
    int am = (g & 1) * 8 + r, ak = (g >> 1) * 8;
    int bn = (g >> 1) * 8 + r, bk = (g & 1) * 8;
#pragma unroll
    for (int ks = 0; ks < 4; ++ks) {
        int kb = ks * 16;
        unsigned Af[4][4], Bf[2];
#pragma unroll
        for (int ms = 0; ms < 4; ++ms) {
            unsigned byte = (unsigned)((wm * 64 + ms * 16 + am) * 128 + (kb + ak) * 2);
            ldsm4(Af[ms], A + sw128(byte));
        }
        unsigned byte = (unsigned)(bn * 128 + (kb + bk) * 2);
        unsigned t[4];
        ldsm4(t, B + sw128(byte));
        Bf[0] = t[0]; Bf[1] = t[1];
#pragma unroll
        for (int ms = 0; ms < 4; ++ms)
            mma_f16(accl[ms], Af[ms], Bf);
    }
}

// acc + add -> gelu -> fp16 -> T tiles (chunk ch @ +ch*16K)
__device__ __forceinline__ void epi_store(float acc[4][4][4], char* T,
                                          const float* __restrict__ addv,
                                          const int* __restrict__ ce, bool perrow,
                                          int wm, int wn, int lid) {
#pragma unroll
    for (int ms = 0; ms < 4; ++ms) {
        int r0 = wm * 64 + ms * 16 + (lid >> 2), r1 = r0 + 8;
#pragma unroll
        for (int ns = 0; ns < 4; ++ns) {
            int n = wn * 32 + ns * 8 + (lid & 3) * 2;
            const float* a0 = perrow ? (addv + (size_t)ce[r0] * 128 + n) : (addv + n);
            const float* a1 = perrow ? (addv + (size_t)ce[r1] * 128 + n) : (addv + n);
            float o0 = gelu_f(acc[ms][ns][0] + a0[0]);
            float o1 = gelu_f(acc[ms][ns][1] + a0[1]);
            float o2 = gelu_f(acc[ms][ns][2] + a1[0]);
            float o3 = gelu_f(acc[ms][ns][3] + a1[1]);
            int ch = n >> 6, kk = n & 63;
            char* th = T + ch * 16384;
            *(unsigned*)(th + sw128((unsigned)(r0 * 128 + kk * 2))) = pack_h2(o0, o1);
            *(unsigned*)(th + sw128((unsigned)(r1 * 128 + kk * 2))) = pack_h2(o2, o3);
        }
    }
}

#define ZERO_ACC(acc) do {                                                    \
    _Pragma("unroll") for (int _i = 0; _i < 4; ++_i)                          \
    _Pragma("unroll") for (int _j = 0; _j < 4; ++_j)                          \
    _Pragma("unroll") for (int _k = 0; _k < 4; ++_k) (acc)[_i][_j][_k] = 0.f; \
} while (0)

// ---------------- setup kernels -----------------------------------------------
extern "C" __global__ void __launch_bounds__(128)
k_init() {
    int i = blockIdx.x * blockDim.x + threadIdx.x;
    if (i < N_NODES * HDIM) g_num[i] = 0.0f;
    if (i < N_NODES * NHEADS) g_den[i] = 0.0f;
}

// hE -> pre-swizzled fp16 tiles; each thread emits one 16B store (full sector)
extern "C" __global__ void __launch_bounds__(256)
k_econv(const float* __restrict__ hE) {
    const float4* hE4 = reinterpret_cast<const float4*>(hE);
    const size_t total = (size_t)EB * 128 * 32;   // 16B units
#pragma unroll
    for (int j = 0; j < 4; ++j) {
        size_t idx = (size_t)blockIdx.x * 1024 + j * 256 + threadIdx.x;
        if (idx >= total) continue;
        size_t e = idx >> 5; int qp = (int)(idx & 31);   // qp: 0..31, q = 2*qp
        int q = qp * 2;
        int c = q >> 4, q15 = q & 15;                    // q15 even
        int m = (int)(e & 127); size_t eb = e >> 7;
        float4 v0 = make_float4(0.f, 0.f, 0.f, 0.f), v1 = v0;
        if (e < N_EDGES) {
            v0 = hE4[e * 64 + (size_t)q];
            v1 = hE4[e * 64 + (size_t)q + 1];
        }
        unsigned sw = sw128((unsigned)(m * 128 + q15 * 8));   // 16B-aligned
        size_t tb = (eb * 4 + (size_t)c) * 16384;
        *(uint4*)(g_hEf + tb + sw) = make_uint4(pack_h2(v0.x, v0.y), pack_h2(v0.z, v0.w),
                                                pack_h2(v1.x, v1.y), pack_h2(v1.z, v1.w));
    }
}

extern "C" __global__ void __launch_bounds__(256)
k_wconv(const float* __restrict__ W, __half* __restrict__ out,
        int nrows_pad, int nrows_real, int nchunks, int rstride, int coff) {
    int idx = blockIdx.x * 256 + threadIdx.x;
    int tile = nrows_pad * 64;
    if (idx >= tile * nchunks) return;
    int c = idx / tile, rem = idx % tile;
    int n = rem / 64, kk = rem % 64;
    float x = (n < nrows_real) ? W[n * rstride + coff + c * 64 + kk] : 0.0f;
    unsigned sw = sw128((unsigned)(n * 128 + kk * 2));
    out[c * tile + sw / 2] = __float2half_rn(x);
}

template<int K, int XP>
__device__ __forceinline__ void gemm_stage(float acc[64], const float* __restrict__ wrow,
                                           const float* __restrict__ xs) {
#pragma unroll 1
    for (int k = 0; k < K; k += 4) {
        float4 wv = *reinterpret_cast<const float4*>(wrow + k);
#pragma unroll
        for (int e = 0; e < 64; ++e) {
            float4 xv = *reinterpret_cast<const float4*>(xs + e * XP + k);
            acc[e] = fmaf(wv.x, xv.x, acc[e]);
            acc[e] = fmaf(wv.y, xv.y, acc[e]);
            acc[e] = fmaf(wv.z, xv.z, acc[e]);
            acc[e] = fmaf(wv.w, xv.w, acc[e]);
        }
    }
}

extern "C" __global__ void __launch_bounds__(128)
k_pre(const float* __restrict__ hV, const float* __restrict__ Wb1,
      const float* __restrict__ bb1) {
    __shared__ float xs[64 * HDIM];
    int j = threadIdx.x;
    int n0 = blockIdx.x * 64;
    int cnt = N_NODES - n0; if (cnt > 64) cnt = 64;
    const float4* src = reinterpret_cast<const float4*>(hV + (size_t)n0 * HDIM);
    float4* dst = reinterpret_cast<float4*>(xs);
    for (int i = j; i < 64 * HDIM / 4; i += 128) {
        int n = i / (HDIM / 4);
        dst[i] = (n < cnt) ? src[i] : make_float4(0.f, 0.f, 0.f, 0.f);
    }
    __syncthreads();
    float acc[64];
    float b = bb1[j];
#pragma unroll
    for (int e = 0; e < 64; ++e) acc[e] = b;
    gemm_stage<HDIM, HDIM>(acc, Wb1 + j * 384, xs);
#pragma unroll
    for (int e = 0; e < 64; ++e)
        if (e < cnt) g_P[(size_t)(n0 + e) * HDIM + j] = acc[e];
}

// ---------------- edge kernel (two-pass, fp16, 2 CTAs/SM) ----------------------
// mode 1 = bias MLP (-> g_ew, g_den); mode 0 = value MLP (-> scatter g_num)
extern "C" __global__ void __launch_bounds__(256, 2)
k_edge(int mode, const int* __restrict__ cid,
       const float* __restrict__ b1, const float* __restrict__ b2,
       const float* __restrict__ b3) {
    extern __shared__ char sm[];
    uint32_t smb = smem_to_u32(sm);
    int tid = threadIdx.x, wid = tid >> 5, lid = tid & 31;
    int wm = wid & 1, wn = wid >> 1;
    size_t e0 = (size_t)blockIdx.x * 128;
    size_t eb = (size_t)blockIdx.x;
    int* ce = (int*)(sm + OFF_CE);
    float* sew = (float*)(sm + OFF_SEW);
    if (tid < 128) ce[tid] = (e0 + tid < N_EDGES) ? cid[e0 + tid] : 0;

    const char* W1 = (const char*)(mode ? g_wb1f : g_wv1f);
    const char* W2 = (const char*)(mode ? g_wb2f : g_wv2f);
    const uint32_t A0 = smb + OFF_A0, A1 = smb + OFF_A1;
    const uint32_t B0 = smb + OFF_B0, B1 = smb + OFF_B1;
    const uint32_t T  = smb + OFF_T;

    float acc[4][4][4];
    ZERO_ACC(acc);

    // ---- L1: hE @ W1^T (K=256, 4 chunks, double-buffered) ----
    cpa16k(A0, g_hEf + eb * 4 * 16384, tid);
    cpa16k(B0, W1, tid);
    CP_COMMIT();                                               // G1
    cpa16k(A1, g_hEf + (eb * 4 + 1) * 16384, tid);
    cpa16k(B1, W1 + 16384, tid);
    CP_COMMIT();                                               // G2
    CP_WAIT1(); __syncthreads();                               // G1 done
    chunk_mma(acc, A0, B0, wm, wn, lid);
    __syncthreads();
    cpa16k(A0, g_hEf + (eb * 4 + 2) * 16384, tid);
    cpa16k(B0, W1 + 32768, tid);
    CP_COMMIT();                                               // G3
    CP_WAIT1(); __syncthreads();                               // G2 done
    chunk_mma(acc, A1, B1, wm, wn, lid);
    __syncthreads();
    cpa16k(A1, g_hEf + (eb * 4 + 3) * 16384, tid);
    cpa16k(B1, W1 + 49152, tid);
    CP_COMMIT();                                               // G4
    CP_WAIT1(); __syncthreads();                               // G3 done
    chunk_mma(acc, A0, B0, wm, wn, lid);
    __syncthreads();
    cpa16k(B0, W2, tid);
    CP_COMMIT();                                               // G5
    CP_WAIT1(); __syncthreads();                               // G4 done
    chunk_mma(acc, A1, B1, wm, wn, lid);
    __syncthreads();
    cpa16k(B1, W2 + 16384, tid);
    CP_COMMIT();                                               // G6
    // t1 = gelu(D + (P[ce] | bv1)) -> T
    epi_store(acc, sm + OFF_T, mode ? g_P : b1, ce, mode != 0, wm, wn, lid);
    __syncthreads();

    // ---- L2: t1 @ W2^T ----
    ZERO_ACC(acc);
    CP_WAIT1(); __syncthreads();                               // G5 done
    chunk_mma(acc, T, B0, wm, wn, lid);
    CP_WAIT0(); __syncthreads();                               // G6 done
    chunk_mma(acc, T + 16384, B1, wm, wn, lid);
    __syncthreads();

    // ---- L3 ----
    if (mode) {
        // Wb3 (4KB) -> B0, overlapped with t2 epilogue
        cp16(B0 + tid * 16, (const char*)g_wb3f + tid * 16);
        CP_COMMIT();
        epi_store(acc, sm + OFF_T, b2, ce, false, wm, wn, lid);   // t2 -> T
        __syncthreads();
        CP_WAIT0(); __syncthreads();
        float accl[4][4];
#pragma unroll
        for (int i = 0; i < 4; ++i)
#pragma unroll
            for (int k = 0; k < 4; ++k) accl[i][k] = 0.f;
        if (wn == 0) {
            chunk_mma_log(accl, T, B0, wm, lid);
            chunk_mma_log(accl, T + 16384, B0 + 2048, wm, lid);
        }
        if (wn == 0 && (lid & 3) < 2) {
            const float rs = 0.17677669529663687f;  // 1/sqrt(32)
            int n = (lid & 3) * 2;
            float bn0 = b3[n], bn1 = b3[n + 1];
#pragma unroll
            for (int ms = 0; ms < 4; ++ms) {
                int r0 = wm * 64 + ms * 16 + (lid >> 2), r1 = r0 + 8;
                float w0 = __expf((accl[ms][0] + bn0) * rs);
                float w1 = __expf((accl[ms][1] + bn1) * rs);
                float w2 = __expf((accl[ms][2] + bn0) * rs);
                float w3 = __expf((accl[ms][3] + bn1) * rs);
                g_ew[(e0 + r0) * 4 + n] = w0;
                g_ew[(e0 + r0) * 4 + n + 1] = w1;
                g_ew[(e0 + r1) * 4 + n] = w2;
                g_ew[(e0 + r1) * 4 + n + 1] = w3;
                if (e0 + r0 < N_EDGES)
                    red2(&g_den[(size_t)ce[r0] * 4 + n], w0, w1);
                if (e0 + r1 < N_EDGES)
                    red2(&g_den[(size_t)ce[r1] * 4 + n], w2, w3);
            }
        }
    } else {
        // Wv3 loads overlapped with t2 epilogue + ew fetch
        cpa16k(B0, (const char*)g_wv3f, tid);
        CP_COMMIT();                                            // G7
        cpa16k(B1, (const char*)g_wv3f + 16384, tid);
        CP_COMMIT();                                            // G8
        epi_store(acc, sm + OFF_T, b2, ce, false, wm, wn, lid);    // t2 -> T
        if (tid < 128)
            *(float4*)(sew + tid * 4) = *(const float4*)(g_ew + (e0 + tid) * 4);
        __syncthreads();
        ZERO_ACC(acc);
        CP_WAIT1(); __syncthreads();                            // G7 done
        chunk_mma(acc, T, B0, wm, wn, lid);
        CP_WAIT0(); __syncthreads();                            // G8 done
        chunk_mma(acc, T + 16384, B1, wm, wn, lid);

#pragma unroll
        for (int ms = 0; ms < 4; ++ms) {
            int r0 = wm * 64 + ms * 16 + (lid >> 2), r1 = r0 + 8;
            float ew0 = sew[r0 * 4 + wn], ew1 = sew[r1 * 4 + wn];
            bool v0 = (e0 + r0) < N_EDGES, v1 = (e0 + r1) < N_EDGES;
            float* d0 = g_num + (size_t)ce[r0] * 128;
            float* d1 = g_num + (size_t)ce[r1] * 128;
#pragma unroll
            for (int ns = 0; ns < 4; ++ns) {
                int n = wn * 32 + ns * 8 + (lid & 3) * 2;
                float bn0 = b3[n], bn1 = b3[n + 1];
                if (v0)
                    red2(d0 + n, ew0 * (acc[ms][ns][0] + bn0),
                                 ew0 * (acc[ms][ns][1] + bn1));
                if (v1)
                    red2(d1 + n, ew1 * (acc[ms][ns][2] + bn0),
                                 ew1 * (acc[ms][ns][3] + bn1));
            }
        }
    }
}

// ---------------- output projection --------------------------------------------
extern "C" __global__ void __launch_bounds__(128)
k_out(const float* __restrict__ Wo, float* __restrict__ out) {
    __shared__ float xs[64 * HDIM];
    int j = threadIdx.x;
    int n0 = blockIdx.x * 64;
    int cnt = N_NODES - n0; if (cnt > 64) cnt = 64;
    for (int i = j; i < 64 * HDIM; i += 128) {
        int n = i >> 7, c = i & 127;
        float v = 0.f;
        if (n < cnt) {
            float d = g_den[(size_t)(n0 + n) * NHEADS + (c >> 5)];
            float nm = g_num[(size_t)(n0 + n) * HDIM + c];
            v = (d > 0.f) ? nm / d : 0.f;
        }
        xs[i] = v;
    }
    __syncthreads();
    float acc[64];
#pragma unroll
    for (int e = 0; e < 64; ++e) acc[e] = 0.f;
    gemm_stage<HDIM, HDIM>(acc, Wo + j * HDIM, xs);
#pragma unroll
    for (int e = 0; e < 64; ++e)
        if (e < cnt) out[(size_t)(n0 + e) * HDIM + j] = acc[e];
}

// ---------------- launch --------------------------------------------------------
extern "C" void kernel_launch(void* const* d_in, const int* in_sizes, int n_in,
                              void* d_out, int out_size) {
    const float* hV  = (const float*)d_in[0];
    const float* hE  = (const float*)d_in[1];
    const float* Wv1 = (const float*)d_in[2];
    const float* bv1 = (const float*)d_in[3];
    const float* Wv2 = (const float*)d_in[4];
    const float* bv2 = (const float*)d_in[5];
    const float* Wv3 = (const float*)d_in[6];
    const float* bv3 = (const float*)d_in[7];
    const float* Wb1 = (const float*)d_in[8];
    const float* bb1 = (const float*)d_in[9];
    const float* Wb2 = (const float*)d_in[10];
    const float* bb2 = (const float*)d_in[11];
    const float* Wb3 = (const float*)d_in[12];
    const float* bb3 = (const float*)d_in[13];
    const float* Wo  = (const float*)d_in[14];
    const int*   cid = (const int*)d_in[15];
    float* out = (float*)d_out;

    __half *wv1f, *wv2f, *wv3f, *wb1f, *wb2f, *wb3f;
    cudaGetSymbolAddress((void**)&wv1f, g_wv1f);
    cudaGetSymbolAddress((void**)&wv2f, g_wv2f);
    cudaGetSymbolAddress((void**)&wv3f, g_wv3f);
    cudaGetSymbolAddress((void**)&wb1f, g_wb1f);
    cudaGetSymbolAddress((void**)&wb2f, g_wb2f);
    cudaGetSymbolAddress((void**)&wb3f, g_wb3f);

    cudaFuncSetAttribute(k_edge, cudaFuncAttributeMaxDynamicSharedMemorySize, SMEM_E);

    k_init<<<(N_NODES * HDIM + 127) / 128, 128>>>();
    k_wconv<<<128, 256>>>(Wv1, wv1f, 128, 128, 4, 256, 0);
    k_wconv<<<64,  256>>>(Wv2, wv2f, 128, 128, 2, 128, 0);
    k_wconv<<<64,  256>>>(Wv3, wv3f, 128, 128, 2, 128, 0);
    k_wconv<<<128, 256>>>(Wb1, wb1f, 128, 128, 4, 384, 128);
    k_wconv<<<64,  256>>>(Wb2, wb2f, 128, 128, 2, 128, 0);
    k_wconv<<<8,   256>>>(Wb3, wb3f, 16, 4, 2, 128, 0);
    k_econv<<<(EB * 128 * 32 + 1023) / 1024, 256>>>(hE);
    k_pre<<<(N_NODES + 63) / 64, 128>>>(hV, Wb1, bb1);

    k_edge<<<EB, 256, SMEM_E>>>(1, cid, bb1, bb2, bb3);   // bias MLP -> ew, den
    k_edge<<<EB, 256, SMEM_E>>>(0, cid, bv1, bv2, bv3);   // value MLP -> num
    k_out<<<(N_NODES + 63) / 64, 128>>>(Wo, out);
}

// round 13
// speedup vs baseline: 2.3374x; 1.0086x over previous
#include <cuda_runtime.h>
#include <cuda_fp16.h>
#include <math.h>
#include <cstdint>

#define N_NODES 20000
#define N_EDGES 600000
#define HDIM 128
#define NHEADS 4
#define EB 4688   // ceil(600000/128)

// ---------------- scratch -----------------------------------------------------
__device__ float g_P[N_NODES * HDIM];
__device__ float g_num[N_NODES * HDIM];
__device__ float g_den[N_NODES * NHEADS];
__device__ float g_ew[(size_t)EB * 128 * NHEADS];   // padded per-edge exp weights

// pre-converted, pre-swizzled fp16 hE tiles: [block][chunk][16KB]
__device__ __align__(16) char g_hEf[(size_t)EB * 4 * 16384];

__device__ __align__(16) __half g_wv1f[32768];
__device__ __align__(16) __half g_wv2f[16384];
__device__ __align__(16) __half g_wv3f[16384];
__device__ __align__(16) __half g_wb1f[32768];
__device__ __align__(16) __half g_wb1pf[16384];   // Wb1[:, :128] (node half) for k_pre2
__device__ __align__(16) __half g_wb2f[16384];
__device__ __align__(16) __half g_wb3f[2048];

// ---------------- helpers -----------------------------------------------------
__device__ __forceinline__ float gelu_f(float x) {
    return 0.5f * x * (1.0f + erff(x * 0.70710678118654752440f));
}
__device__ __forceinline__ uint32_t smem_to_u32(const void* p) {
    uint32_t a;
    asm("{ .reg .u64 t; cvta.to.shared.u64 t, %1; cvt.u32.u64 %0, t; }" : "=r"(a) : "l"(p));
    return a;
}
__device__ __forceinline__ unsigned sw128(unsigned byte) {
    return byte ^ ((byte >> 3) & 0x70);
}
__device__ __forceinline__ unsigned pack_h2(float a, float b) {
    __half2 h = __floats2half2_rn(a, b);
    return *reinterpret_cast<unsigned*>(&h);
}
// vectorized global reductions (base PTX, sm_90+)
__device__ __forceinline__ void red2(float* addr, float a, float b) {
    asm volatile("red.global.add.v2.f32 [%0], {%1, %2};"
                 :: "l"(addr), "f"(a), "f"(b) : "memory");
}
__device__ __forceinline__ void red4(float* addr, float a, float b, float c, float d) {
    asm volatile("red.global.add.v4.f32 [%0], {%1, %2, %3, %4};"
                 :: "l"(addr), "f"(a), "f"(b), "f"(c), "f"(d) : "memory");
}

// ---------------- cp.async ------------------------------------------------------
__device__ __forceinline__ void cp16(uint32_t dst, const void* src) {
    asm volatile("cp.async.cg.shared.global [%0], [%1], 16;" :: "r"(dst), "l"(src));
}
#define CP_COMMIT() asm volatile("cp.async.commit_group;" ::: "memory")
#define CP_WAIT0()  asm volatile("cp.async.wait_group 0;" ::: "memory")
#define CP_WAIT1()  asm volatile("cp.async.wait_group 1;" ::: "memory")

__device__ __forceinline__ void cpa16k(uint32_t dst, const char* src, int tid) {
#pragma unroll
    for (int j = 0; j < 4; ++j)
        cp16(dst + tid * 16 + j * 4096, src + tid * 16 + j * 4096);
}

// ---------------- mma.sync primitives ------------------------------------------
__device__ __forceinline__ void ldsm4(unsigned r[4], uint32_t addr) {
    asm volatile("ldmatrix.sync.aligned.m8n8.x4.shared.b16 {%0,%1,%2,%3}, [%4];"
        : "=r"(r[0]), "=r"(r[1]), "=r"(r[2]), "=r"(r[3]) : "r"(addr));
}
__device__ __forceinline__ void mma_f16(float c[4], const unsigned a[4], const unsigned b[2]) {
    asm volatile("mma.sync.aligned.m16n8k16.row.col.f32.f16.f16.f32 "
        "{%0,%1,%2,%3}, {%4,%5,%6,%7}, {%8,%9}, {%0,%1,%2,%3};"
        : "+f"(c[0]), "+f"(c[1]), "+f"(c[2]), "+f"(c[3])
        : "r"(a[0]), "r"(a[1]), "r"(a[2]), "r"(a[3]), "r"(b[0]), "r"(b[1]));
}

// smem byte offsets (total 102400 -> 2 CTAs/SM)
#define OFF_CE   0
#define OFF_SEW  512
#define OFF_B0   4096
#define OFF_B1   20480
#define OFF_A0   36864
#define OFF_A1   53248
#define OFF_T    69632      /* 2 chunks x 16KB */
#define SMEM_E   102400
#define SMEM_P   65536

// one K=64 chunk, single fp16 pass; tiles 128x64 fp16 SW128 (128B pitch)
__device__ __forceinline__ void chunk_mma(float acc[4][4][4],
                                          uint32_t A, uint32_t B,
                                          int wm, int wn, int lid) {
    int g = lid >> 3, r = lid & 7;
    int am = (g & 1) * 8 + r, ak = (g >> 1) * 8;
    int bn = (g >> 1) * 8 + r, bk = (g & 1) * 8;
#pragma unroll
    for (int ks = 0; ks < 4; ++ks) {
        int kb = ks * 16;
        unsigned Af[4][4], Bf[4][2];
#pragma unroll
        for (int ms = 0; ms < 4; ++ms) {
            unsigned byte = (unsigned)((wm * 64 + ms * 16 + am) * 128 + (kb + ak) * 2);
            ldsm4(Af[ms], A + sw128(byte));
        }
#pragma unroll
        for (int np = 0; np < 2; ++np) {
            unsigned byte = (unsigned)((wn * 32 + np * 16 + bn) * 128 + (kb + bk) * 2);
            unsigned t[4];
            ldsm4(t, B + sw128(byte));
            Bf[np*2][0] = t[0]; Bf[np*2][1] = t[1];
            Bf[np*2+1][0] = t[2]; Bf[np*2+1][1] = t[3];
        }
#pragma unroll
        for (int ms = 0; ms < 4; ++ms)
#pragma unroll
            for (int ns = 0; ns < 4; ++ns)
                mma_f16(acc[ms][ns], Af[ms], Bf[ns]);
    }
}

// logits variant: n0-7 only, B tile 16-row padded (2KB per chunk)
__device__ __forceinline__ void chunk_mma_log(float accl[4][4],
                                              uint32_t A, uint32_t B,
                                              int wm, int lid) {
    int g = lid >> 3, r = lid & 7;
    int am = (g & 1) * 8 + r, ak = (g >> 1) * 8;
    int bn = (g >> 1) * 8 + r, bk = (g & 1) * 8;
#pragma unroll
    for (int ks = 0; ks < 4; ++ks) {
        int kb = ks * 16;
        unsigned Af[4][4], Bf[2];
#pragma unroll
        for (int ms = 0; ms < 4; ++ms) {
            unsigned byte = (unsigned)((wm * 64 + ms * 16 + am) * 128 + (kb + ak) * 2);
            ldsm4(Af[ms], A + sw128(byte));
        }
        unsigned byte = (unsigned)(bn * 128 + (kb + bk) * 2);
        unsigned t[4];
        ldsm4(t, B + sw128(byte));
        Bf[0] = t[0]; Bf[1] = t[1];
#pragma unroll
        for (int ms = 0; ms < 4; ++ms)
            mma_f16(accl[ms], Af[ms], Bf);
    }
}

// acc + add -> gelu -> fp16 -> T tiles (chunk ch @ +ch*16K)
__device__ __forceinline__ void epi_store(float acc[4][4][4], char* T,
                                          const float* __restrict__ addv,
                                          const int* __restrict__ ce, bool perrow,
                                          int wm, int wn, int lid) {
#pragma unroll
    for (int ms = 0; ms < 4; ++ms) {
        int r0 = wm * 64 + ms * 16 + (lid >> 2), r1 = r0 + 8;
#pragma unroll
        for (int ns = 0; ns < 4; ++ns) {
            int n = wn * 32 + ns * 8 + (lid & 3) * 2;
            const float* a0 = perrow ? (addv + (size_t)ce[r0] * 128 + n) : (addv + n);
            const float* a1 = perrow ? (addv + (size_t)ce[r1] * 128 + n) : (addv + n);
            float o0 = gelu_f(acc[ms][ns][0] + a0[0]);
            float o1 = gelu_f(acc[ms][ns][1] + a0[1]);
            float o2 = gelu_f(acc[ms][ns][2] + a1[0]);
            float o3 = gelu_f(acc[ms][ns][3] + a1[1]);
            int ch = n >> 6, kk = n & 63;
            char* th = T + ch * 16384;
            *(unsigned*)(th + sw128((unsigned)(r0 * 128 + kk * 2))) = pack_h2(o0, o1);
            *(unsigned*)(th + sw128((unsigned)(r1 * 128 + kk * 2))) = pack_h2(o2, o3);
        }
    }
}

#define ZERO_ACC(acc) do {                                                    \
    _Pragma("unroll") for (int _i = 0; _i < 4; ++_i)                          \
    _Pragma("unroll") for (int _j = 0; _j < 4; ++_j)                          \
    _Pragma("unroll") for (int _k = 0; _k < 4; ++_k) (acc)[_i][_j][_k] = 0.f; \
} while (0)

// ---------------- setup kernels -----------------------------------------------
extern "C" __global__ void __launch_bounds__(128)
k_init() {
    int i = blockIdx.x * blockDim.x + threadIdx.x;
    if (i < N_NODES * HDIM) g_num[i] = 0.0f;
    if (i < N_NODES * NHEADS) g_den[i] = 0.0f;
}

// hE -> pre-swizzled fp16 tiles; each thread emits one 16B store (full sector)
extern "C" __global__ void __launch_bounds__(256)
k_econv(const float* __restrict__ hE) {
    const float4* hE4 = reinterpret_cast<const float4*>(hE);
    const size_t total = (size_t)EB * 128 * 32;   // 16B units
#pragma unroll
    for (int j = 0; j < 4; ++j) {
        size_t idx = (size_t)blockIdx.x * 1024 + j * 256 + threadIdx.x;
        if (idx >= total) continue;
        size_t e = idx >> 5; int qp = (int)(idx & 31);
        int q = qp * 2;
        int c = q >> 4, q15 = q & 15;
        int m = (int)(e & 127); size_t eb = e >> 7;
        float4 v0 = make_float4(0.f, 0.f, 0.f, 0.f), v1 = v0;
        if (e < N_EDGES) {
            v0 = hE4[e * 64 + (size_t)q];
            v1 = hE4[e * 64 + (size_t)q + 1];
        }
        unsigned sw = sw128((unsigned)(m * 128 + q15 * 8));
        size_t tb = (eb * 4 + (size_t)c) * 16384;
        *(uint4*)(g_hEf + tb + sw) = make_uint4(pack_h2(v0.x, v0.y), pack_h2(v0.z, v0.w),
                                                pack_h2(v1.x, v1.y), pack_h2(v1.z, v1.w));
    }
}

extern "C" __global__ void __launch_bounds__(256)
k_wconv(const float* __restrict__ W, __half* __restrict__ out,
        int nrows_pad, int nrows_real, int nchunks, int rstride, int coff) {
    int idx = blockIdx.x * 256 + threadIdx.x;
    int tile = nrows_pad * 64;
    if (idx >= tile * nchunks) return;
    int c = idx / tile, rem = idx % tile;
    int n = rem / 64, kk = rem % 64;
    float x = (n < nrows_real) ? W[n * rstride + coff + c * 64 + kk] : 0.0f;
    unsigned sw = sw128((unsigned)(n * 128 + kk * 2));
    out[c * tile + sw / 2] = __float2half_rn(x);
}

template<int K, int XP>
__device__ __forceinline__ void gemm_stage(float acc[64], const float* __restrict__ wrow,
                                           const float* __restrict__ xs) {
#pragma unroll 1
    for (int k = 0; k < K; k += 4) {
        float4 wv = *reinterpret_cast<const float4*>(wrow + k);
#pragma unroll
        for (int e = 0; e < 64; ++e) {
            float4 xv = *reinterpret_cast<const float4*>(xs + e * XP + k);
            acc[e] = fmaf(wv.x, xv.x, acc[e]);
            acc[e] = fmaf(wv.y, xv.y, acc[e]);
            acc[e] = fmaf(wv.z, xv.z, acc[e]);
            acc[e] = fmaf(wv.w, xv.w, acc[e]);
        }
    }
}

// P = hV @ Wb1[:, :128]^T + bb1 via fp16 HMMA (M=128 nodes per CTA)
extern "C" __global__ void __launch_bounds__(256)
k_pre2(const float* __restrict__ hV, const float* __restrict__ bb1) {
    extern __shared__ char sm[];
    uint32_t smb = smem_to_u32(sm);
    int tid = threadIdx.x, wid = tid >> 5, lid = tid & 31;
    int wm = wid & 1, wn = wid >> 1;
    int n0 = blockIdx.x * 128;

    cpa16k(smb + 32768, (const char*)g_wb1pf, tid);
    cpa16k(smb + 49152, (const char*)g_wb1pf + 16384, tid);
    CP_COMMIT();

    const float4* hv4 = reinterpret_cast<const float4*>(hV);
    for (int u = tid; u < 4096; u += 256) {
        int m = u >> 5, q = u & 31;
        int c = q >> 4, q15 = q & 15;
        float4 v = make_float4(0.f, 0.f, 0.f, 0.f);
        if (n0 + m < N_NODES) v = hv4[(size_t)(n0 + m) * 32 + q];
        *(uint2*)(sm + c * 16384 + sw128((unsigned)(m * 128 + q15 * 8))) =
            make_uint2(pack_h2(v.x, v.y), pack_h2(v.z, v.w));
    }
    CP_WAIT0();
    __syncthreads();

    float acc[4][4][4];
    ZERO_ACC(acc);
    chunk_mma(acc, smb,         smb + 32768, wm, wn, lid);
    chunk_mma(acc, smb + 16384, smb + 49152, wm, wn, lid);

#pragma unroll
    for (int ms = 0; ms < 4; ++ms) {
        int r0 = wm * 64 + ms * 16 + (lid >> 2), r1 = r0 + 8;
#pragma unroll
        for (int ns = 0; ns < 4; ++ns) {
            int n = wn * 32 + ns * 8 + (lid & 3) * 2;
            float b0 = bb1[n], b1v = bb1[n + 1];
            if (n0 + r0 < N_NODES) {
                g_P[(size_t)(n0 + r0) * 128 + n]     = acc[ms][ns][0] + b0;
                g_P[(size_t)(n0 + r0) * 128 + n + 1] = acc[ms][ns][1] + b1v;
            }
            if (n0 + r1 < N_NODES) {
                g_P[(size_t)(n0 + r1) * 128 + n]     = acc[ms][ns][2] + b0;
                g_P[(size_t)(n0 + r1) * 128 + n + 1] = acc[ms][ns][3] + b1v;
            }
        }
    }
}

// ---------------- edge kernel (two-pass, fp16, 2 CTAs/SM) ----------------------
// mode 1 = bias MLP (-> g_ew, g_den); mode 0 = value MLP (-> scatter g_num)
extern "C" __global__ void __launch_bounds__(256, 2)
k_edge(int mode, const int* __restrict__ cid,
       const float* __restrict__ b1, const float* __restrict__ b2,
       const float* __restrict__ b3) {
    extern __shared__ char sm[];
    uint32_t smb = smem_to_u32(sm);
    int tid = threadIdx.x, wid = tid >> 5, lid = tid & 31;
    int wm = wid & 1, wn = wid >> 1;
    size_t e0 = (size_t)blockIdx.x * 128;
    size_t eb = (size_t)blockIdx.x;
    int* ce = (int*)(sm + OFF_CE);
    float* sew = (float*)(sm + OFF_SEW);
    if (tid < 128) ce[tid] = (e0 + tid < N_EDGES) ? cid[e0 + tid] : 0;

    const char* W1 = (const char*)(mode ? g_wb1f : g_wv1f);
    const char* W2 = (const char*)(mode ? g_wb2f : g_wv2f);
    const uint32_t A0 = smb + OFF_A0, A1 = smb + OFF_A1;
    const uint32_t B0 = smb + OFF_B0, B1 = smb + OFF_B1;
    const uint32_t T  = smb + OFF_T;

    float acc[4][4][4];
    ZERO_ACC(acc);

    // ---- L1: hE @ W1^T (K=256, 4 chunks, double-buffered) ----
    cpa16k(A0, g_hEf + eb * 4 * 16384, tid);
    cpa16k(B0, W1, tid);
    CP_COMMIT();                                               // G1
    cpa16k(A1, g_hEf + (eb * 4 + 1) * 16384, tid);
    cpa16k(B1, W1 + 16384, tid);
    CP_COMMIT();                                               // G2
    CP_WAIT1(); __syncthreads();                               // G1 done
    chunk_mma(acc, A0, B0, wm, wn, lid);
    __syncthreads();
    cpa16k(A0, g_hEf + (eb * 4 + 2) * 16384, tid);
    cpa16k(B0, W1 + 32768, tid);
    CP_COMMIT();                                               // G3
    CP_WAIT1(); __syncthreads();                               // G2 done
    chunk_mma(acc, A1, B1, wm, wn, lid);
    __syncthreads();
    cpa16k(A1, g_hEf + (eb * 4 + 3) * 16384, tid);
    cpa16k(B1, W1 + 49152, tid);
    CP_COMMIT();                                               // G4
    CP_WAIT1(); __syncthreads();                               // G3 done
    chunk_mma(acc, A0, B0, wm, wn, lid);
    __syncthreads();
    cpa16k(B0, W2, tid);
    CP_COMMIT();                                               // G5
    CP_WAIT1(); __syncthreads();                               // G4 done
    chunk_mma(acc, A1, B1, wm, wn, lid);
    __syncthreads();
    cpa16k(B1, W2 + 16384, tid);
    CP_COMMIT();                                               // G6
    // t1 = gelu(D + (P[ce] | bv1)) -> T
    epi_store(acc, sm + OFF_T, mode ? g_P : b1, ce, mode != 0, wm, wn, lid);
    __syncthreads();

    // ---- L2: t1 @ W2^T ----
    ZERO_ACC(acc);
    CP_WAIT1(); __syncthreads();                               // G5 done
    chunk_mma(acc, T, B0, wm, wn, lid);
    CP_WAIT0(); __syncthreads();                               // G6 done
    chunk_mma(acc, T + 16384, B1, wm, wn, lid);
    __syncthreads();

    // ---- L3 ----
    if (mode) {
        // Wb3 (4KB) -> B0, overlapped with t2 epilogue
        cp16(B0 + tid * 16, (const char*)g_wb3f + tid * 16);
        CP_COMMIT();
        epi_store(acc, sm + OFF_T, b2, ce, false, wm, wn, lid);   // t2 -> T
        __syncthreads();
        CP_WAIT0(); __syncthreads();
        float accl[4][4];
#pragma unroll
        for (int i = 0; i < 4; ++i)
#pragma unroll
            for (int k = 0; k < 4; ++k) accl[i][k] = 0.f;
        if (wn == 0) {
            chunk_mma_log(accl, T, B0, wm, lid);
            chunk_mma_log(accl, T + 16384, B0 + 2048, wm, lid);
        }
        if (wn == 0 && (lid & 3) < 2) {
            const float rs = 0.17677669529663687f;  // 1/sqrt(32)
            int n = (lid & 3) * 2;
            float bn0 = b3[n], bn1 = b3[n + 1];
#pragma unroll
            for (int ms = 0; ms < 4; ++ms) {
                int r0 = wm * 64 + ms * 16 + (lid >> 2), r1 = r0 + 8;
                float w0 = __expf((accl[ms][0] + bn0) * rs);
                float w1 = __expf((accl[ms][1] + bn1) * rs);
                float w2 = __expf((accl[ms][2] + bn0) * rs);
                float w3 = __expf((accl[ms][3] + bn1) * rs);
                g_ew[(e0 + r0) * 4 + n] = w0;
                g_ew[(e0 + r0) * 4 + n + 1] = w1;
                g_ew[(e0 + r1) * 4 + n] = w2;
                g_ew[(e0 + r1) * 4 + n + 1] = w3;
                if (e0 + r0 < N_EDGES)
                    red2(&g_den[(size_t)ce[r0] * 4 + n], w0, w1);
                if (e0 + r1 < N_EDGES)
                    red2(&g_den[(size_t)ce[r1] * 4 + n], w2, w3);
            }
        }
    } else {
        // Wv3 loads overlapped with t2 epilogue + ew fetch
        cpa16k(B0, (const char*)g_wv3f, tid);
        CP_COMMIT();                                            // G7
        cpa16k(B1, (const char*)g_wv3f + 16384, tid);
        CP_COMMIT();                                            // G8
        epi_store(acc, sm + OFF_T, b2, ce, false, wm, wn, lid);    // t2 -> T
        if (tid < 128)
            *(float4*)(sew + tid * 4) = *(const float4*)(g_ew + (e0 + tid) * 4);
        __syncthreads();
        ZERO_ACC(acc);
        CP_WAIT1(); __syncthreads();                            // G7 done
        chunk_mma(acc, T, B0, wm, wn, lid);
        CP_WAIT0(); __syncthreads();                            // G8 done
        chunk_mma(acc, T + 16384, B1, wm, wn, lid);

        // scatter: lane-pair shuffle -> 16B red.v4 (even lanes: r0, odd: r1)
        int odd = lid & 1;
#pragma unroll
        for (int ms = 0; ms < 4; ++ms) {
            int r0 = wm * 64 + ms * 16 + (lid >> 2), r1 = r0 + 8;
            float ew0 = sew[r0 * 4 + wn], ew1 = sew[r1 * 4 + wn];
            bool v0 = (e0 + r0) < N_EDGES, v1 = (e0 + r1) < N_EDGES;
            float* d0 = g_num + (size_t)ce[r0] * 128;
            float* d1 = g_num + (size_t)ce[r1] * 128;
#pragma unroll
            for (int ns = 0; ns < 4; ++ns) {
                int n = wn * 32 + ns * 8 + (lid & 3) * 2;
                float b0 = b3[n], b1v = b3[n + 1];
                float x0 = acc[ms][ns][0] + b0, x1 = acc[ms][ns][1] + b1v;
                float x2 = acc[ms][ns][2] + b0, x3 = acc[ms][ns][3] + b1v;
                float s0 = __shfl_xor_sync(0xffffffffu, odd ? x0 : x2, 1);
                float s1 = __shfl_xor_sync(0xffffffffu, odd ? x1 : x3, 1);
                if (!odd) {
                    if (v0) red4(d0 + n, ew0 * x0, ew0 * x1, ew0 * s0, ew0 * s1);
                } else {
                    if (v1) red4(d1 + n - 2, ew1 * s0, ew1 * s1, ew1 * x2, ew1 * x3);
                }
            }
        }
    }
}

// ---------------- output projection --------------------------------------------
extern "C" __global__ void __launch_bounds__(128)
k_out(const float* __restrict__ Wo, float* __restrict__ out) {
    __shared__ float xs[64 * HDIM];
    int j = threadIdx.x;
    int n0 = blockIdx.x * 64;
    int cnt = N_NODES - n0; if (cnt > 64) cnt = 64;
    for (int i = j; i < 64 * HDIM; i += 128) {
        int n = i >> 7, c = i & 127;
        float v = 0.f;
        if (n < cnt) {
            float d = g_den[(size_t)(n0 + n) * NHEADS + (c >> 5)];
            float nm = g_num[(size_t)(n0 + n) * HDIM + c];
            v = (d > 0.f) ? nm / d : 0.f;
        }
        xs[i] = v;
    }
    __syncthreads();
    float acc[64];
#pragma unroll
    for (int e = 0; e < 64; ++e) acc[e] = 0.f;
    gemm_stage<HDIM, HDIM>(acc, Wo + j * HDIM, xs);
#pragma unroll
    for (int e = 0; e < 64; ++e)
        if (e < cnt) out[(size_t)(n0 + e) * HDIM + j] = acc[e];
}

// ---------------- launch --------------------------------------------------------
extern "C" void kernel_launch(void* const* d_in, const int* in_sizes, int n_in,
                              void* d_out, int out_size) {
    const float* hV  = (const float*)d_in[0];
    const float* hE  = (const float*)d_in[1];
    const float* Wv1 = (const float*)d_in[2];
    const float* bv1 = (const float*)d_in[3];
    const float* Wv2 = (const float*)d_in[4];
    const float* bv2 = (const float*)d_in[5];
    const float* Wv3 = (const float*)d_in[6];
    const float* bv3 = (const float*)d_in[7];
    const float* Wb1 = (const float*)d_in[8];
    const float* bb1 = (const float*)d_in[9];
    const float* Wb2 = (const float*)d_in[10];
    const float* bb2 = (const float*)d_in[11];
    const float* Wb3 = (const float*)d_in[12];
    const float* bb3 = (const float*)d_in[13];
    const float* Wo  = (const float*)d_in[14];
    const int*   cid = (const int*)d_in[15];
    float* out = (float*)d_out;

    __half *wv1f, *wv2f, *wv3f, *wb1f, *wb1pf, *wb2f, *wb3f;
    cudaGetSymbolAddress((void**)&wv1f, g_wv1f);
    cudaGetSymbolAddress((void**)&wv2f, g_wv2f);
    cudaGetSymbolAddress((void**)&wv3f, g_wv3f);
    cudaGetSymbolAddress((void**)&wb1f, g_wb1f);
    cudaGetSymbolAddress((void**)&wb1pf, g_wb1pf);
    cudaGetSymbolAddress((void**)&wb2f, g_wb2f);
    cudaGetSymbolAddress((void**)&wb3f, g_wb3f);

    cudaFuncSetAttribute(k_edge, cudaFuncAttributeMaxDynamicSharedMemorySize, SMEM_E);
    cudaFuncSetAttribute(k_pre2, cudaFuncAttributeMaxDynamicSharedMemorySize, SMEM_P);

    k_init<<<(N_NODES * HDIM + 127) / 128, 128>>>();
    k_wconv<<<128, 256>>>(Wv1, wv1f, 128, 128, 4, 256, 0);
    k_wconv<<<64,  256>>>(Wv2, wv2f, 128, 128, 2, 128, 0);
    k_wconv<<<64,  256>>>(Wv3, wv3f, 128, 128, 2, 128, 0);
    k_wconv<<<128, 256>>>(Wb1, wb1f, 128, 128, 4, 384, 128);
    k_wconv<<<64,  256>>>(Wb1, wb1pf, 128, 128, 2, 384, 0);
    k_wconv<<<64,  256>>>(Wb2, wb2f, 128, 128, 2, 128, 0);
    k_wconv<<<8,   256>>>(Wb3, wb3f, 16, 4, 2, 128, 0);
    k_econv<<<(EB * 128 * 32 + 1023) / 1024, 256>>>(hE);
    k_pre2<<<(N_NODES + 127) / 128, 256, SMEM_P>>>(hV, bb1);

    k_edge<<<EB, 256, SMEM_E>>>(1, cid, bb1, bb2, bb3);   // bias MLP -> ew, den
    k_edge<<<EB, 256, SMEM_E>>>(0, cid, bv1, bv2, bv3);   // value MLP -> num
    k_out<<<(N_NODES + 63) / 64, 128>>>(Wo, out);
}

// round 14
// speedup vs baseline: 2.3643x; 1.0115x over previous
#include <cuda_runtime.h>
#include <cuda_fp16.h>
#include <math.h>
#include <cstdint>

#define N_NODES 20000
#define N_EDGES 600000
#define HDIM 128
#define NHEADS 4
#define EB 4688   // ceil(600000/128)

// ---------------- scratch -----------------------------------------------------
__device__ float g_P[N_NODES * HDIM];
__device__ float g_num[N_NODES * HDIM];
__device__ float g_den[N_NODES * NHEADS];
__device__ float g_ew[(size_t)EB * 128 * NHEADS];   // padded per-edge exp weights

// pre-converted, pre-swizzled fp16 hE tiles: [block][chunk][16KB]
__device__ __align__(16) char g_hEf[(size_t)EB * 4 * 16384];

__device__ __align__(16) __half g_wv1f[32768];
__device__ __align__(16) __half g_wv2f[16384];
__device__ __align__(16) __half g_wv3f[16384];
__device__ __align__(16) __half g_wb1f[32768];
__device__ __align__(16) __half g_wb1pf[16384];   // Wb1[:, :128] (node half) for k_pre2
__device__ __align__(16) __half g_wb2f[16384];
__device__ __align__(16) __half g_wb3f[2048];

// ---------------- helpers -----------------------------------------------------
__device__ __forceinline__ float gelu_f(float x) {
    return 0.5f * x * (1.0f + erff(x * 0.70710678118654752440f));
}
__device__ __forceinline__ uint32_t smem_to_u32(const void* p) {
    uint32_t a;
    asm("{ .reg .u64 t; cvta.to.shared.u64 t, %1; cvt.u32.u64 %0, t; }" : "=r"(a) : "l"(p));
    return a;
}
__device__ __forceinline__ unsigned sw128(unsigned byte) {
    return byte ^ ((byte >> 3) & 0x70);
}
__device__ __forceinline__ unsigned pack_h2(float a, float b) {
    __half2 h = __floats2half2_rn(a, b);
    return *reinterpret_cast<unsigned*>(&h);
}
// vectorized global reductions (base PTX, sm_90+)
__device__ __forceinline__ void red2(float* addr, float a, float b) {
    asm volatile("red.global.add.v2.f32 [%0], {%1, %2};"
                 :: "l"(addr), "f"(a), "f"(b) : "memory");
}
__device__ __forceinline__ void red4(float* addr, float a, float b, float c, float d) {
    asm volatile("red.global.add.v4.f32 [%0], {%1, %2, %3, %4};"
                 :: "l"(addr), "f"(a), "f"(b), "f"(c), "f"(d) : "memory");
}

// ---------------- cp.async ------------------------------------------------------
__device__ __forceinline__ void cp16(uint32_t dst, const void* src) {
    asm volatile("cp.async.cg.shared.global [%0], [%1], 16;" :: "r"(dst), "l"(src));
}
#define CP_COMMIT() asm volatile("cp.async.commit_group;" ::: "memory")
#define CP_WAIT0()  asm volatile("cp.async.wait_group 0;" ::: "memory")
#define CP_WAIT1()  asm volatile("cp.async.wait_group 1;" ::: "memory")

__device__ __forceinline__ void cpa16k(uint32_t dst, const char* src, int tid) {
#pragma unroll
    for (int j = 0; j < 4; ++j)
        cp16(dst + tid * 16 + j * 4096, src + tid * 16 + j * 4096);
}

// ---------------- mma.sync primitives ------------------------------------------
__device__ __forceinline__ void ldsm4(unsigned r[4], uint32_t addr) {
    asm volatile("ldmatrix.sync.aligned.m8n8.x4.shared.b16 {%0,%1,%2,%3}, [%4];"
        : "=r"(r[0]), "=r"(r[1]), "=r"(r[2]), "=r"(r[3]) : "r"(addr));
}
__device__ __forceinline__ void mma_f16(float c[4], const unsigned a[4], const unsigned b[2]) {
    asm volatile("mma.sync.aligned.m16n8k16.row.col.f32.f16.f16.f32 "
        "{%0,%1,%2,%3}, {%4,%5,%6,%7}, {%8,%9}, {%0,%1,%2,%3};"
        : "+f"(c[0]), "+f"(c[1]), "+f"(c[2]), "+f"(c[3])
        : "r"(a[0]), "r"(a[1]), "r"(a[2]), "r"(a[3]), "r"(b[0]), "r"(b[1]));
}

// smem byte offsets (total 102400 -> 2 CTAs/SM)
#define OFF_CE   0
#define OFF_SEW  512
#define OFF_B0   4096
#define OFF_B1   20480
#define OFF_A0   36864
#define OFF_A1   53248
#define OFF_T    69632      /* 2 chunks x 16KB */
#define SMEM_E   102400
#define SMEM_P   65536

// one K=64 chunk, single fp16 pass; tiles 128x64 fp16 SW128 (128B pitch)
__device__ __forceinline__ void chunk_mma(float acc[4][4][4],
                                          uint32_t A, uint32_t B,
                                          int wm, int wn, int lid) {
    int g = lid >> 3, r = lid & 7;
    int am = (g & 1) * 8 + r, ak = (g >> 1) * 8;
    int bn = (g >> 1) * 8 + r, bk = (g & 1) * 8;
#pragma unroll
    for (int ks = 0; ks < 4; ++ks) {
        int kb = ks * 16;
        unsigned Af[4][4], Bf[4][2];
#pragma unroll
        for (int ms = 0; ms < 4; ++ms) {
            unsigned byte = (unsigned)((wm * 64 + ms * 16 + am) * 128 + (kb + ak) * 2);
            ldsm4(Af[ms], A + sw128(byte));
        }
#pragma unroll
        for (int np = 0; np < 2; ++np) {
            unsigned byte = (unsigned)((wn * 32 + np * 16 + bn) * 128 + (kb + bk) * 2);
            unsigned t[4];
            ldsm4(t, B + sw128(byte));
            Bf[np*2][0] = t[0]; Bf[np*2][1] = t[1];
            Bf[np*2+1][0] = t[2]; Bf[np*2+1][1] = t[3];
        }
#pragma unroll
        for (int ms = 0; ms < 4; ++ms)
#pragma unroll
            for (int ns = 0; ns < 4; ++ns)
                mma_f16(acc[ms][ns], Af[ms], Bf[ns]);
    }
}

// logits variant: n0-7 only, B tile 16-row padded (2KB per chunk)
__device__ __forceinline__ void chunk_mma_log(float accl[4][4],
                                              uint32_t A, uint32_t B,
                                              int wm, int lid) {
    int g = lid >> 3, r = lid & 7;
    int am = (g & 1) * 8 + r, ak = (g >> 1) * 8;
    int bn = (g >> 1) * 8 + r, bk = (g & 1) * 8;
#pragma unroll
    for (int ks = 0; ks < 4; ++ks) {
        int kb = ks * 16;
        unsigned Af[4][4], Bf[2];
#pragma unroll
        for (int ms = 0; ms < 4; ++ms) {
            unsigned byte = (unsigned)((wm * 64 + ms * 16 + am) * 128 + (kb + ak) * 2);
            ldsm4(Af[ms], A + sw128(byte));
        }
        unsigned byte = (unsigned)(bn * 128 + (kb + bk) * 2);
        unsigned t[4];
        ldsm4(t, B + sw128(byte));
        Bf[0] = t[0]; Bf[1] = t[1];
#pragma unroll
        for (int ms = 0; ms < 4; ++ms)
            mma_f16(accl[ms], Af[ms], Bf);
    }
}

// acc + add -> gelu -> fp16 -> T tiles (chunk ch @ +ch*16K)
__device__ __forceinline__ void epi_store(float acc[4][4][4], char* T,
                                          const float* __restrict__ addv,
                                          const int* __restrict__ ce, bool perrow,
                                          int wm, int wn, int lid) {
#pragma unroll
    for (int ms = 0; ms < 4; ++ms) {
        int r0 = wm * 64 + ms * 16 + (lid >> 2), r1 = r0 + 8;
#pragma unroll
        for (int ns = 0; ns < 4; ++ns) {
            int n = wn * 32 + ns * 8 + (lid & 3) * 2;
            const float* a0 = perrow ? (addv + (size_t)ce[r0] * 128 + n) : (addv + n);
            const float* a1 = perrow ? (addv + (size_t)ce[r1] * 128 + n) : (addv + n);
            float o0 = gelu_f(acc[ms][ns][0] + a0[0]);
            float o1 = gelu_f(acc[ms][ns][1] + a0[1]);
            float o2 = gelu_f(acc[ms][ns][2] + a1[0]);
            float o3 = gelu_f(acc[ms][ns][3] + a1[1]);
            int ch = n >> 6, kk = n & 63;
            char* th = T + ch * 16384;
            *(unsigned*)(th + sw128((unsigned)(r0 * 128 + kk * 2))) = pack_h2(o0, o1);
            *(unsigned*)(th + sw128((unsigned)(r1 * 128 + kk * 2))) = pack_h2(o2, o3);
        }
    }
}

#define ZERO_ACC(acc) do {                                                    \
    _Pragma("unroll") for (int _i = 0; _i < 4; ++_i)                          \
    _Pragma("unroll") for (int _j = 0; _j < 4; ++_j)                          \
    _Pragma("unroll") for (int _k = 0; _k < 4; ++_k) (acc)[_i][_j][_k] = 0.f; \
} while (0)

// ---------------- setup kernels -----------------------------------------------
extern "C" __global__ void __launch_bounds__(128)
k_init() {
    int i = blockIdx.x * blockDim.x + threadIdx.x;
    if (i < N_NODES * HDIM) g_num[i] = 0.0f;
    if (i < N_NODES * NHEADS) g_den[i] = 0.0f;
}

// ALL weight conversions in one launch (block-range table).
// Ranges: [0,128) Wv1 | [128,192) Wv2 | [192,256) Wv3 | [256,384) Wb1e |
//         [384,448) Wb1p | [448,512) Wb2 | [512,520) Wb3
extern "C" __global__ void __launch_bounds__(256)
k_wconv_all(const float* __restrict__ Wv1, const float* __restrict__ Wv2,
            const float* __restrict__ Wv3, const float* __restrict__ Wb1,
            const float* __restrict__ Wb2, const float* __restrict__ Wb3) {
    int b = blockIdx.x, tid = threadIdx.x;
    const float* W; __half* out;
    int pad = 128, real = 128, nch, rs, co = 0, lb;
    if (b < 128)      { W = Wv1; out = g_wv1f;  nch = 4; rs = 256; lb = b; }
    else if (b < 192) { W = Wv2; out = g_wv2f;  nch = 2; rs = 128; lb = b - 128; }
    else if (b < 256) { W = Wv3; out = g_wv3f;  nch = 2; rs = 128; lb = b - 192; }
    else if (b < 384) { W = Wb1; out = g_wb1f;  nch = 4; rs = 384; co = 128; lb = b - 256; }
    else if (b < 448) { W = Wb1; out = g_wb1pf; nch = 2; rs = 384; lb = b - 384; }
    else if (b < 512) { W = Wb2; out = g_wb2f;  nch = 2; rs = 128; lb = b - 448; }
    else              { W = Wb3; out = g_wb3f;  nch = 2; rs = 128; pad = 16; real = 4; lb = b - 512; }
    int idx = lb * 256 + tid;
    int tile = pad * 64;
    if (idx >= tile * nch) return;
    int c = idx / tile, rem = idx % tile;
    int n = rem / 64, kk = rem % 64;
    float x = (n < real) ? W[n * rs + co + c * 64 + kk] : 0.0f;
    unsigned sw = sw128((unsigned)(n * 128 + kk * 2));
    out[c * tile + sw / 2] = __float2half_rn(x);
}

// hE -> pre-swizzled fp16 tiles; each thread emits one 16B store (full sector)
extern "C" __global__ void __launch_bounds__(256)
k_econv(const float* __restrict__ hE) {
    const float4* hE4 = reinterpret_cast<const float4*>(hE);
    const size_t total = (size_t)EB * 128 * 32;   // 16B units
#pragma unroll
    for (int j = 0; j < 4; ++j) {
        size_t idx = (size_t)blockIdx.x * 1024 + j * 256 + threadIdx.x;
        if (idx >= total) continue;
        size_t e = idx >> 5; int qp = (int)(idx & 31);
        int q = qp * 2;
        int c = q >> 4, q15 = q & 15;
        int m = (int)(e & 127); size_t eb = e >> 7;
        float4 v0 = make_float4(0.f, 0.f, 0.f, 0.f), v1 = v0;
        if (e < N_EDGES) {
            v0 = hE4[e * 64 + (size_t)q];
            v1 = hE4[e * 64 + (size_t)q + 1];
        }
        unsigned sw = sw128((unsigned)(m * 128 + q15 * 8));
        size_t tb = (eb * 4 + (size_t)c) * 16384;
        *(uint4*)(g_hEf + tb + sw) = make_uint4(pack_h2(v0.x, v0.y), pack_h2(v0.z, v0.w),
                                                pack_h2(v1.x, v1.y), pack_h2(v1.z, v1.w));
    }
}

template<int K, int XP>
__device__ __forceinline__ void gemm_stage(float acc[64], const float* __restrict__ wrow,
                                           const float* __restrict__ xs) {
#pragma unroll 1
    for (int k = 0; k < K; k += 4) {
        float4 wv = *reinterpret_cast<const float4*>(wrow + k);
#pragma unroll
        for (int e = 0; e < 64; ++e) {
            float4 xv = *reinterpret_cast<const float4*>(xs + e * XP + k);
            acc[e] = fmaf(wv.x, xv.x, acc[e]);
            acc[e] = fmaf(wv.y, xv.y, acc[e]);
            acc[e] = fmaf(wv.z, xv.z, acc[e]);
            acc[e] = fmaf(wv.w, xv.w, acc[e]);
        }
    }
}

// P = hV @ Wb1[:, :128]^T + bb1 via fp16 HMMA (M=128 nodes per CTA)
extern "C" __global__ void __launch_bounds__(256)
k_pre2(const float* __restrict__ hV, const float* __restrict__ bb1) {
    extern __shared__ char sm[];
    uint32_t smb = smem_to_u32(sm);
    int tid = threadIdx.x, wid = tid >> 5, lid = tid & 31;
    int wm = wid & 1, wn = wid >> 1;
    int n0 = blockIdx.x * 128;

    cpa16k(smb + 32768, (const char*)g_wb1pf, tid);
    cpa16k(smb + 49152, (const char*)g_wb1pf + 16384, tid);
    CP_COMMIT();

    const float4* hv4 = reinterpret_cast<const float4*>(hV);
    for (int u = tid; u < 4096; u += 256) {
        int m = u >> 5, q = u & 31;
        int c = q >> 4, q15 = q & 15;
        float4 v = make_float4(0.f, 0.f, 0.f, 0.f);
        if (n0 + m < N_NODES) v = hv4[(size_t)(n0 + m) * 32 + q];
        *(uint2*)(sm + c * 16384 + sw128((unsigned)(m * 128 + q15 * 8))) =
            make_uint2(pack_h2(v.x, v.y), pack_h2(v.z, v.w));
    }
    CP_WAIT0();
    __syncthreads();

    float acc[4][4][4];
    ZERO_ACC(acc);
    chunk_mma(acc, smb,         smb + 32768, wm, wn, lid);
    chunk_mma(acc, smb + 16384, smb + 49152, wm, wn, lid);

#pragma unroll
    for (int ms = 0; ms < 4; ++ms) {
        int r0 = wm * 64 + ms * 16 + (lid >> 2), r1 = r0 + 8;
#pragma unroll
        for (int ns = 0; ns < 4; ++ns) {
            int n = wn * 32 + ns * 8 + (lid & 3) * 2;
            float b0 = bb1[n], b1v = bb1[n + 1];
            if (n0 + r0 < N_NODES) {
                g_P[(size_t)(n0 + r0) * 128 + n]     = acc[ms][ns][0] + b0;
                g_P[(size_t)(n0 + r0) * 128 + n + 1] = acc[ms][ns][1] + b1v;
            }
            if (n0 + r1 < N_NODES) {
                g_P[(size_t)(n0 + r1) * 128 + n]     = acc[ms][ns][2] + b0;
                g_P[(size_t)(n0 + r1) * 128 + n + 1] = acc[ms][ns][3] + b1v;
            }
        }
    }
}

// ---------------- edge kernel (two-pass, fp16, 2 CTAs/SM) ----------------------
// mode 1 = bias MLP (-> g_ew, g_den); mode 0 = value MLP (-> scatter g_num)
extern "C" __global__ void __launch_bounds__(256, 2)
k_edge(int mode, const int* __restrict__ cid,
       const float* __restrict__ b1, const float* __restrict__ b2,
       const float* __restrict__ b3) {
    extern __shared__ char sm[];
    uint32_t smb = smem_to_u32(sm);
    int tid = threadIdx.x, wid = tid >> 5, lid = tid & 31;
    int wm = wid & 1, wn = wid >> 1;
    size_t e0 = (size_t)blockIdx.x * 128;
    size_t eb = (size_t)blockIdx.x;
    int* ce = (int*)(sm + OFF_CE);
    float* sew = (float*)(sm + OFF_SEW);
    if (tid < 128) ce[tid] = (e0 + tid < N_EDGES) ? cid[e0 + tid] : 0;

    const char* W1 = (const char*)(mode ? g_wb1f : g_wv1f);
    const char* W2 = (const char*)(mode ? g_wb2f : g_wv2f);
    const uint32_t A0 = smb + OFF_A0, A1 = smb + OFF_A1;
    const uint32_t B0 = smb + OFF_B0, B1 = smb + OFF_B1;
    const uint32_t T  = smb + OFF_T;

    float acc[4][4][4];
    ZERO_ACC(acc);

    // ---- L1: hE @ W1^T (K=256, 4 chunks, double-buffered) ----
    cpa16k(A0, g_hEf + eb * 4 * 16384, tid);
    cpa16k(B0, W1, tid);
    CP_COMMIT();                                               // G1
    cpa16k(A1, g_hEf + (eb * 4 + 1) * 16384, tid);
    cpa16k(B1, W1 + 16384, tid);
    CP_COMMIT();                                               // G2
    CP_WAIT1(); __syncthreads();                               // G1 done
    chunk_mma(acc, A0, B0, wm, wn, lid);
    __syncthreads();
    cpa16k(A0, g_hEf + (eb * 4 + 2) * 16384, tid);
    cpa16k(B0, W1 + 32768, tid);
    CP_COMMIT();                                               // G3
    CP_WAIT1(); __syncthreads();                               // G2 done
    chunk_mma(acc, A1, B1, wm, wn, lid);
    __syncthreads();
    cpa16k(A1, g_hEf + (eb * 4 + 3) * 16384, tid);
    cpa16k(B1, W1 + 49152, tid);
    CP_COMMIT();                                               // G4
    CP_WAIT1(); __syncthreads();                               // G3 done
    chunk_mma(acc, A0, B0, wm, wn, lid);
    __syncthreads();
    cpa16k(B0, W2, tid);
    CP_COMMIT();                                               // G5
    CP_WAIT1(); __syncthreads();                               // G4 done
    chunk_mma(acc, A1, B1, wm, wn, lid);
    __syncthreads();
    cpa16k(B1, W2 + 16384, tid);
    CP_COMMIT();                                               // G6
    // t1 = gelu(D + (P[ce] | bv1)) -> T
    epi_store(acc, sm + OFF_T, mode ? g_P : b1, ce, mode != 0, wm, wn, lid);
    __syncthreads();

    // ---- L2: t1 @ W2^T ----
    ZERO_ACC(acc);
    CP_WAIT1(); __syncthreads();                               // G5 done
    chunk_mma(acc, T, B0, wm, wn, lid);
    CP_WAIT0(); __syncthreads();                               // G6 done
    chunk_mma(acc, T + 16384, B1, wm, wn, lid);
    __syncthreads();

    // ---- L3 ----
    if (mode) {
        // Wb3 (4KB) -> B0, overlapped with t2 epilogue
        cp16(B0 + tid * 16, (const char*)g_wb3f + tid * 16);
        CP_COMMIT();
        epi_store(acc, sm + OFF_T, b2, ce, false, wm, wn, lid);   // t2 -> T
        __syncthreads();
        CP_WAIT0(); __syncthreads();
        float accl[4][4];
#pragma unroll
        for (int i = 0; i < 4; ++i)
#pragma unroll
            for (int k = 0; k < 4; ++k) accl[i][k] = 0.f;
        if (wn == 0) {
            chunk_mma_log(accl, T, B0, wm, lid);
            chunk_mma_log(accl, T + 16384, B0 + 2048, wm, lid);
        }
        if (wn == 0 && (lid & 3) < 2) {
            const float rs = 0.17677669529663687f;  // 1/sqrt(32)
            int n = (lid & 3) * 2;
            float bn0 = b3[n], bn1 = b3[n + 1];
#pragma unroll
            for (int ms = 0; ms < 4; ++ms) {
                int r0 = wm * 64 + ms * 16 + (lid >> 2), r1 = r0 + 8;
                float w0 = __expf((accl[ms][0] + bn0) * rs);
                float w1 = __expf((accl[ms][1] + bn1) * rs);
                float w2 = __expf((accl[ms][2] + bn0) * rs);
                float w3 = __expf((accl[ms][3] + bn1) * rs);
                g_ew[(e0 + r0) * 4 + n] = w0;
                g_ew[(e0 + r0) * 4 + n + 1] = w1;
                g_ew[(e0 + r1) * 4 + n] = w2;
                g_ew[(e0 + r1) * 4 + n + 1] = w3;
                if (e0 + r0 < N_EDGES)
                    red2(&g_den[(size_t)ce[r0] * 4 + n], w0, w1);
                if (e0 + r1 < N_EDGES)
                    red2(&g_den[(size_t)ce[r1] * 4 + n], w2, w3);
            }
        }
    } else {
        // Wv3 loads overlapped with t2 epilogue + ew fetch
        cpa16k(B0, (const char*)g_wv3f, tid);
        CP_COMMIT();                                            // G7
        cpa16k(B1, (const char*)g_wv3f + 16384, tid);
        CP_COMMIT();                                            // G8
        epi_store(acc, sm + OFF_T, b2, ce, false, wm, wn, lid);    // t2 -> T
        if (tid < 128)
            *(float4*)(sew + tid * 4) = *(const float4*)(g_ew + (e0 + tid) * 4);
        __syncthreads();
        ZERO_ACC(acc);
        CP_WAIT1(); __syncthreads();                            // G7 done
        chunk_mma(acc, T, B0, wm, wn, lid);
        CP_WAIT0(); __syncthreads();                            // G8 done
        chunk_mma(acc, T + 16384, B1, wm, wn, lid);

        // scatter: lane-pair shuffle -> 16B red.v4 (even lanes: r0, odd: r1)
        int odd = lid & 1;
#pragma unroll
        for (int ms = 0; ms < 4; ++ms) {
            int r0 = wm * 64 + ms * 16 + (lid >> 2), r1 = r0 + 8;
            float ew0 = sew[r0 * 4 + wn], ew1 = sew[r1 * 4 + wn];
            bool v0 = (e0 + r0) < N_EDGES, v1 = (e0 + r1) < N_EDGES;
            float* d0 = g_num + (size_t)ce[r0] * 128;
            float* d1 = g_num + (size_t)ce[r1] * 128;
#pragma unroll
            for (int ns = 0; ns < 4; ++ns) {
                int n = wn * 32 + ns * 8 + (lid & 3) * 2;
                float b0 = b3[n], b1v = b3[n + 1];
                float x0 = acc[ms][ns][0] + b0, x1 = acc[ms][ns][1] + b1v;
                float x2 = acc[ms][ns][2] + b0, x3 = acc[ms][ns][3] + b1v;
                float s0 = __shfl_xor_sync(0xffffffffu, odd ? x0 : x2, 1);
                float s1 = __shfl_xor_sync(0xffffffffu, odd ? x1 : x3, 1);
                if (!odd) {
                    if (v0) red4(d0 + n, ew0 * x0, ew0 * x1, ew0 * s0, ew0 * s1);
                } else {
                    if (v1) red4(d1 + n - 2, ew1 * s0, ew1 * s1, ew1 * x2, ew1 * x3);
                }
            }
        }
    }
}

// ---------------- output projection --------------------------------------------
extern "C" __global__ void __launch_bounds__(128)
k_out(const float* __restrict__ Wo, float* __restrict__ out) {
    __shared__ float xs[64 * HDIM];
    int j = threadIdx.x;
    int n0 = blockIdx.x * 64;
    int cnt = N_NODES - n0; if (cnt > 64) cnt = 64;
    for (int i = j; i < 64 * HDIM; i += 128) {
        int n = i >> 7, c = i & 127;
        float v = 0.f;
        if (n < cnt) {
            float d = g_den[(size_t)(n0 + n) * NHEADS + (c >> 5)];
            float nm = g_num[(size_t)(n0 + n) * HDIM + c];
            v = (d > 0.f) ? nm / d : 0.f;
        }
        xs[i] = v;
    }
    __syncthreads();
    float acc[64];
#pragma unroll
    for (int e = 0; e < 64; ++e) acc[e] = 0.f;
    gemm_stage<HDIM, HDIM>(acc, Wo + j * HDIM, xs);
#pragma unroll
    for (int e = 0; e < 64; ++e)
        if (e < cnt) out[(size_t)(n0 + e) * HDIM + j] = acc[e];
}

// ---------------- launch --------------------------------------------------------
extern "C" void kernel_launch(void* const* d_in, const int* in_sizes, int n_in,
                              void* d_out, int out_size) {
    const float* hV  = (const float*)d_in[0];
    const float* hE  = (const float*)d_in[1];
    const float* Wv1 = (const float*)d_in[2];
    const float* bv1 = (const float*)d_in[3];
    const float* Wv2 = (const float*)d_in[4];
    const float* bv2 = (const float*)d_in[5];
    const float* Wv3 = (const float*)d_in[6];
    const float* bv3 = (const float*)d_in[7];
    const float* Wb1 = (const float*)d_in[8];
    const float* bb1 = (const float*)d_in[9];
    const float* Wb2 = (const float*)d_in[10];
    const float* bb2 = (const float*)d_in[11];
    const float* Wb3 = (const float*)d_in[12];
    const float* bb3 = (const float*)d_in[13];
    const float* Wo  = (const float*)d_in[14];
    const int*   cid = (const int*)d_in[15];
    float* out = (float*)d_out;

    cudaFuncSetAttribute(k_edge, cudaFuncAttributeMaxDynamicSharedMemorySize, SMEM_E);
    cudaFuncSetAttribute(k_pre2, cudaFuncAttributeMaxDynamicSharedMemorySize, SMEM_P);

    // launch order fixed so ncu (-s 5 -c 1) profiles the value-pass k_edge:
    // [0] k_init [1] k_wconv_all [2] k_econv [3] k_pre2 [4] k_edge(bias)
    // [5] k_edge(value) <- profiled  [6] k_out
    k_init<<<(N_NODES * HDIM + 127) / 128, 128>>>();
    k_wconv_all<<<520, 256>>>(Wv1, Wv2, Wv3, Wb1, Wb2, Wb3);
    k_econv<<<(EB * 128 * 32 + 1023) / 1024, 256>>>(hE);
    k_pre2<<<(N_NODES + 127) / 128, 256, SMEM_P>>>(hV, bb1);
    k_edge<<<EB, 256, SMEM_E>>>(1, cid, bb1, bb2, bb3);   // bias MLP -> ew, den
    k_edge<<<EB, 256, SMEM_E>>>(0, cid, bv1, bv2, bv3);   // value MLP -> num
    k_out<<<(N_NODES + 63) / 64, 128>>>(Wo, out);
}